// round 9
// baseline (speedup 1.0000x reference)
#include <cuda_runtime.h>
#include <cuda_bf16.h>
#include <math.h>
#include <stdint.h>

#define N_MAX   100000
#define E_MAX   3300000
#define IN_CH   512
#define H1F     64      // heads1*ch1
#define OUT_CH  16
#define KSTEPS  32      // 512 / 16

// ---------------- device scratch (no allocation allowed) ----------------
__device__ float g_h1  [(size_t)N_MAX * H1F];    // x@W1
__device__ float g_e1s [(size_t)N_MAX * 8];
__device__ float g_e1d [(size_t)N_MAX * 8];
__device__ float g_hact[(size_t)N_MAX * H1F];    // elu(layer1 out)
__device__ float g_h2  [(size_t)N_MAX * OUT_CH]; // hact@W2
__device__ float g_e2s [N_MAX];
__device__ float g_e2d [N_MAX];
__device__ int   g_deg [N_MAX];
__device__ int   g_off [N_MAX + 1];
__device__ int   g_cur [N_MAX];
__device__ int   g_csr [E_MAX];
__device__ int   g_bsum[128];
// W1 pre-packed into mma B-fragment layout (bf16 hi / lo), [ks][nfp][lane]
__device__ uint4 g_wp_h[KSTEPS * 4 * 32];
__device__ uint4 g_wp_l[KSTEPS * 4 * 32];

// ---------------- bf16 split helpers ----------------
// hi = truncate-to-bf16 (top 16 bits); pack pair {f0 -> low half, f1 -> high half}
__device__ __forceinline__ uint32_t hi_pack(float f0, float f1) {
    return __byte_perm(__float_as_uint(f0), __float_as_uint(f1), 0x7632);
}
__device__ __forceinline__ uint32_t lo_pack(float f0, float f1) {
    float l0 = f0 - __uint_as_float(__float_as_uint(f0) & 0xffff0000u);
    float l1 = f1 - __uint_as_float(__float_as_uint(f1) & 0xffff0000u);
    uint32_t r;
    asm("cvt.rn.bf16x2.f32 %0, %1, %2;" : "=r"(r) : "f"(l1), "f"(l0));  // first src -> high half
    return r;
}
__device__ __forceinline__ void mma_bf16(float* d,
                                         uint32_t a0, uint32_t a1, uint32_t a2, uint32_t a3,
                                         uint32_t b0, uint32_t b1) {
    asm("mma.sync.aligned.m16n8k16.row.col.f32.bf16.bf16.f32 "
        "{%0,%1,%2,%3}, {%4,%5,%6,%7}, {%8,%9}, {%0,%1,%2,%3};"
        : "+f"(d[0]), "+f"(d[1]), "+f"(d[2]), "+f"(d[3])
        : "r"(a0), "r"(a1), "r"(a2), "r"(a3), "r"(b0), "r"(b1));
}
__device__ __forceinline__ uint32_t smem_u32(const void* p) {
    uint32_t a;
    asm("{ .reg .u64 t; cvta.to.shared.u64 t, %1; cvt.u32.u64 %0, t; }" : "=r"(a) : "l"(p));
    return a;
}
__device__ __forceinline__ void cpa16(uint32_t dst, const void* src) {
    asm volatile("cp.async.ca.shared.global [%0], [%1], 16;" :: "r"(dst), "l"(src));
}

// ---------------- packed f32x2 helpers (for gemm2) ----------------
__device__ __forceinline__ void fma_f32x2(unsigned long long& acc,
                                          unsigned long long a, unsigned long long b) {
    asm("fma.rn.f32x2 %0, %1, %2, %0;" : "+l"(acc) : "l"(a), "l"(b));
}
__device__ __forceinline__ unsigned long long pack_ff(float v) {
    unsigned long long r;
    asm("mov.b64 %0, {%1, %1};" : "=l"(r) : "f"(v));
    return r;
}
__device__ __forceinline__ void unpack_ff(unsigned long long p, float& lo, float& hi) {
    asm("mov.b64 {%0, %1}, %2;" : "=f"(lo), "=f"(hi) : "l"(p));
}

// ---------------- CSR build ----------------
__global__ void k_zero(int N) {
    int i = blockIdx.x * blockDim.x + threadIdx.x;
    if (i < N) g_deg[i] = 0;
}

__global__ void k_deg(const int* __restrict__ ei, int E_orig, int E_tot) {
    int i = blockIdx.x * blockDim.x + threadIdx.x;
    if (i >= E_tot) return;
    int dst = (i < E_orig) ? ei[E_orig + i] : (i - E_orig);
    atomicAdd(&g_deg[dst], 1);
}

__global__ void k_scanA(int N) {      // grid: ceil(N/1024), block 1024
    __shared__ int s[1024];
    int tid = threadIdx.x;
    int i = blockIdx.x * 1024 + tid;
    int v = (i < N) ? g_deg[i] : 0;
    s[tid] = v;
    __syncthreads();
    for (int o = 1; o < 1024; o <<= 1) {
        int t = (tid >= o) ? s[tid - o] : 0;
        __syncthreads();
        s[tid] += t;
        __syncthreads();
    }
    if (i < N) g_off[i + 1] = s[tid];
    if (tid == 1023) g_bsum[blockIdx.x] = s[1023];
}

__global__ void k_scanB(int nb) {     // <<<1,1>>>
    int run = 0;
    for (int b = 0; b < nb; b++) {
        int t = g_bsum[b];
        g_bsum[b] = run;
        run += t;
    }
}

__global__ void k_scanC(int N) {
    int i = blockIdx.x * blockDim.x + threadIdx.x;
    if (i < N) g_off[i + 1] += g_bsum[i >> 10];
    if (i == 0) g_off[0] = 0;
}

__global__ void k_cursor(int N) {
    int i = blockIdx.x * blockDim.x + threadIdx.x;
    if (i < N) g_cur[i] = g_off[i];
}

__global__ void k_scatter(const int* __restrict__ ei, int E_orig, int E_tot) {
    int i = blockIdx.x * blockDim.x + threadIdx.x;
    if (i >= E_tot) return;
    int src, dst;
    if (i < E_orig) { src = ei[i]; dst = ei[E_orig + i]; }
    else            { src = i - E_orig; dst = src; }
    int p = atomicAdd(&g_cur[dst], 1);
    g_csr[p] = src;
}

// ---------------- W1 pre-pack into B-fragment layout ----------------
// B frag (m16n8k16, col): lane l (g=l>>2, t=l&3): b0={B[2t][g],B[2t+1][g]},
// b1={B[2t+8][g],B[2t+9][g]}. uint4 per (ks,nfp,lane) = {nf0.b0, nf0.b1, nf1.b0, nf1.b1}.
__global__ void k_wsplit(const float* __restrict__ W1) {
    int i = blockIdx.x * blockDim.x + threadIdx.x;   // 0 .. 4095
    if (i >= KSTEPS * 4 * 32) return;
    int ks  = i >> 7;
    int nfp = (i >> 5) & 3;
    int l   = i & 31;
    int g = l >> 2, t = l & 3;
    uint32_t h[4], lo[4];
#pragma unroll
    for (int j = 0; j < 4; j++) {
        int nf  = nfp * 2 + (j >> 1);
        int reg = j & 1;
        int k0  = ks * 16 + 2 * t + reg * 8;
        int col = nf * 8 + g;
        float w0 = W1[k0 * 64 + col];
        float w1 = W1[(k0 + 1) * 64 + col];
        h[j]  = hi_pack(w0, w1);
        lo[j] = lo_pack(w0, w1);
    }
    g_wp_h[i] = make_uint4(h[0], h[1], h[2], h[3]);
    g_wp_l[i] = make_uint4(lo[0], lo[1], lo[2], lo[3]);
}

// ---------------- GEMM1 via mma.sync + cp.async smem pipeline ----------------
// CTA = 128 rows; per k-step an 8KB x tile (128 x 16 fp32) is staged through a
// 4-deep cp.async ring. A-frags from smem (LDS.64), B-frags from L1-hot
// pre-packed globals. Warp = 16 rows x 64 cols. bf16 hi/lo split (3 MMAs).
#define G1_STRIDE 20                    // floats per staged row (16 data + 4 pad)
#define G1_STAGE  (128 * G1_STRIDE)     // 2560 floats = 10240 B
#define G1_SMEM   (4 * G1_STAGE * 4)    // 40960 B

__global__ __launch_bounds__(256, 4) void k_gemm1(
    const float* __restrict__ x,
    const float* __restrict__ a1s, const float* __restrict__ a1d, int N)
{
    extern __shared__ float sx[];
    const uint32_t sb_u = smem_u32(sx);
    int t    = threadIdx.x;
    int wid  = t >> 5;
    int lane = t & 31;
    int g = lane >> 2, q = lane & 3;
    int n0 = blockIdx.x * 128;

    // producer geometry: 2 x 16B chunks per thread per stage
    int row0 = t >> 2, c4 = t & 3;      // chunk0: rows 0..63
    int row1 = row0 + 64;               // chunk1: rows 64..127
    int gn0 = n0 + row0; if (gn0 >= N) gn0 = 0;
    int gn1 = n0 + row1; if (gn1 >= N) gn1 = 0;
    const float* src0 = x + (size_t)gn0 * IN_CH + c4 * 4;
    const float* src1 = x + (size_t)gn1 * IN_CH + c4 * 4;
    uint32_t dst0 = sb_u + (uint32_t)(row0 * G1_STRIDE + c4 * 4) * 4;
    uint32_t dst1 = sb_u + (uint32_t)(row1 * G1_STRIDE + c4 * 4) * 4;

    // consumer geometry
    int rA = wid * 16 + g;
    int rB = rA + 8;
    int ofA0 = rA * G1_STRIDE + 2 * q;
    int ofB0 = rB * G1_STRIDE + 2 * q;

    float acc[8][4];
#pragma unroll
    for (int h = 0; h < 8; h++)
#pragma unroll
        for (int c = 0; c < 4; c++) acc[h][c] = 0.f;

    // prologue: stages 0..2 in flight
#pragma unroll
    for (int s = 0; s < 3; s++) {
        uint32_t bo = (uint32_t)(s * G1_STAGE) * 4;
        cpa16(dst0 + bo, src0 + s * 16);
        cpa16(dst1 + bo, src1 + s * 16);
        asm volatile("cp.async.commit_group;");
    }

    for (int ks = 0; ks < KSTEPS; ks++) {
        // groups committed so far: 0..ks+2; <=2 pending => group ks done
        asm volatile("cp.async.wait_group 2;");
        __syncthreads();   // stage ks visible; all warps consumed stage ks-1
        {
            int kn = ks + 3;
            if (kn < KSTEPS) {
                uint32_t bo = (uint32_t)((kn & 3) * G1_STAGE) * 4;
                cpa16(dst0 + bo, src0 + kn * 16);
                cpa16(dst1 + bo, src1 + kn * 16);
            }
            asm volatile("cp.async.commit_group;");   // empty group past the end
        }
        const float* sb = sx + (ks & 3) * G1_STAGE;
        float2 f0 = *reinterpret_cast<const float2*>(sb + ofA0);
        float2 f1 = *reinterpret_cast<const float2*>(sb + ofB0);
        float2 f2 = *reinterpret_cast<const float2*>(sb + ofA0 + 8);
        float2 f3 = *reinterpret_cast<const float2*>(sb + ofB0 + 8);
        uint32_t ah0 = hi_pack(f0.x, f0.y), ah1 = hi_pack(f1.x, f1.y);
        uint32_t ah2 = hi_pack(f2.x, f2.y), ah3 = hi_pack(f3.x, f3.y);
        uint32_t al0 = lo_pack(f0.x, f0.y), al1 = lo_pack(f1.x, f1.y);
        uint32_t al2 = lo_pack(f2.x, f2.y), al3 = lo_pack(f3.x, f3.y);

        const uint4* wph = &g_wp_h[ks * 128 + lane];
        const uint4* wpl = &g_wp_l[ks * 128 + lane];
#pragma unroll
        for (int nfp = 0; nfp < 4; nfp++) {
            uint4 wh = wph[nfp * 32];
            uint4 wl = wpl[nfp * 32];
            mma_bf16(acc[2 * nfp],     ah0, ah1, ah2, ah3, wh.x, wh.y);
            mma_bf16(acc[2 * nfp],     ah0, ah1, ah2, ah3, wl.x, wl.y);
            mma_bf16(acc[2 * nfp],     al0, al1, al2, al3, wh.x, wh.y);
            mma_bf16(acc[2 * nfp + 1], ah0, ah1, ah2, ah3, wh.z, wh.w);
            mma_bf16(acc[2 * nfp + 1], ah0, ah1, ah2, ah3, wl.z, wl.w);
            mma_bf16(acc[2 * nfp + 1], al0, al1, al2, al3, wh.z, wh.w);
        }
    }

    // epilogue: store h1, compute e1s/e1d per head via quad reduction
    int r0 = n0 + rA, r1 = n0 + rB;
    bool ok0 = (r0 < N), ok1 = (r1 < N);
#pragma unroll
    for (int h = 0; h < 8; h++) {
        if (ok0)
            *reinterpret_cast<float2*>(&g_h1[(size_t)r0 * H1F + h * 8 + 2 * q]) =
                make_float2(acc[h][0], acc[h][1]);
        if (ok1)
            *reinterpret_cast<float2*>(&g_h1[(size_t)r1 * H1F + h * 8 + 2 * q]) =
                make_float2(acc[h][2], acc[h][3]);
        float2 s = *reinterpret_cast<const float2*>(&a1s[h * 8 + 2 * q]);
        float2 d = *reinterpret_cast<const float2*>(&a1d[h * 8 + 2 * q]);
        float es0 = acc[h][0] * s.x + acc[h][1] * s.y;
        float ed0 = acc[h][0] * d.x + acc[h][1] * d.y;
        float es1 = acc[h][2] * s.x + acc[h][3] * s.y;
        float ed1 = acc[h][2] * d.x + acc[h][3] * d.y;
        es0 += __shfl_xor_sync(0xffffffffu, es0, 1);
        es0 += __shfl_xor_sync(0xffffffffu, es0, 2);
        ed0 += __shfl_xor_sync(0xffffffffu, ed0, 1);
        ed0 += __shfl_xor_sync(0xffffffffu, ed0, 2);
        es1 += __shfl_xor_sync(0xffffffffu, es1, 1);
        es1 += __shfl_xor_sync(0xffffffffu, es1, 2);
        ed1 += __shfl_xor_sync(0xffffffffu, ed1, 1);
        ed1 += __shfl_xor_sync(0xffffffffu, ed1, 2);
        if (q == 0) {
            if (ok0) { g_e1s[r0 * 8 + h] = es0; g_e1d[r0 * 8 + h] = ed0; }
            if (ok1) { g_e1s[r1 * 8 + h] = es1; g_e1d[r1 * 8 + h] = ed1; }
        }
    }
}

// ---------------- layer-1 edge aggregation (warp per dst, unroll x2) ----------
// No segment-max needed: logits are O(1), exp() is safe, and
// alpha = exp(l)/sum exp(l) is identical to the max-subtracted form.
__global__ void k_edge1(const float* __restrict__ b1, int N) {
    int w = (blockIdx.x * blockDim.x + threadIdx.x) >> 5;
    if (w >= N) return;
    int lane = threadIdx.x & 31;
    int h0 = lane >> 3;              // feature f0=lane -> head lane/8
    const float ed0 = g_e1d[w * 8 + h0];
    const float ed1 = g_e1d[w * 8 + 4 + h0];   // f1 = lane+32 -> head 4+lane/8
    int beg = g_off[w], end = g_off[w + 1];
    float acc0 = 0.f, acc1 = 0.f, dn0 = 0.f, dn1 = 0.f;
    int i = beg;
    for (; i + 2 <= end; i += 2) {
        int sA = __ldg(&g_csr[i]);
        int sB = __ldg(&g_csr[i + 1]);
        float tA0 = __ldg(&g_e1s[sA * 8 + h0]) + ed0;
        float tA1 = __ldg(&g_e1s[sA * 8 + 4 + h0]) + ed1;
        float tB0 = __ldg(&g_e1s[sB * 8 + h0]) + ed0;
        float tB1 = __ldg(&g_e1s[sB * 8 + 4 + h0]) + ed1;
        float hA0 = __ldg(&g_h1[(size_t)sA * H1F + lane]);
        float hA1 = __ldg(&g_h1[(size_t)sA * H1F + 32 + lane]);
        float hB0 = __ldg(&g_h1[(size_t)sB * H1F + lane]);
        float hB1 = __ldg(&g_h1[(size_t)sB * H1F + 32 + lane]);
        tA0 = tA0 > 0.f ? tA0 : 0.2f * tA0;
        tA1 = tA1 > 0.f ? tA1 : 0.2f * tA1;
        tB0 = tB0 > 0.f ? tB0 : 0.2f * tB0;
        tB1 = tB1 > 0.f ? tB1 : 0.2f * tB1;
        float wA0 = __expf(tA0), wA1 = __expf(tA1);
        float wB0 = __expf(tB0), wB1 = __expf(tB1);
        acc0 = fmaf(wA0, hA0, acc0); dn0 += wA0;
        acc1 = fmaf(wA1, hA1, acc1); dn1 += wA1;
        acc0 = fmaf(wB0, hB0, acc0); dn0 += wB0;
        acc1 = fmaf(wB1, hB1, acc1); dn1 += wB1;
    }
    if (i < end) {
        int s = __ldg(&g_csr[i]);
        float t0 = __ldg(&g_e1s[s * 8 + h0]) + ed0;
        float t1 = __ldg(&g_e1s[s * 8 + 4 + h0]) + ed1;
        t0 = t0 > 0.f ? t0 : 0.2f * t0;
        t1 = t1 > 0.f ? t1 : 0.2f * t1;
        float w0 = __expf(t0);
        float w1 = __expf(t1);
        acc0 = fmaf(w0, __ldg(&g_h1[(size_t)s * H1F + lane]), acc0);
        acc1 = fmaf(w1, __ldg(&g_h1[(size_t)s * H1F + 32 + lane]), acc1);
        dn0 += w0; dn1 += w1;
    }
    float v0 = acc0 / dn0 + b1[lane];
    float v1 = acc1 / dn1 + b1[lane + 32];
    v0 = v0 > 0.f ? v0 : (__expf(v0) - 1.f);   // ELU
    v1 = v1 > 0.f ? v1 : (__expf(v1) - 1.f);
    g_hact[(size_t)w * H1F + lane]      = v0;
    g_hact[(size_t)w * H1F + 32 + lane] = v1;
}

// ---------------- GEMM2: h2 = hact @ W2 (+ e2_src/e2_dst), packed f32x2 -------
__global__ __launch_bounds__(256) void k_gemm2(
    const float* __restrict__ W2, const float* __restrict__ a2s,
    const float* __restrict__ a2d, int N)
{
    __shared__ float hs[64 * 65];
    __shared__ float ws[64 * 16];
    __shared__ float h2s[64 * 17];
    int t  = threadIdx.x;
    int n0 = blockIdx.x * 64;
#pragma unroll
    for (int r = 0; r < 4; r++) {
        int f4   = t + r * 256;
        int node = f4 >> 4;
        int k4   = f4 & 15;
        int gn   = n0 + node;
        float4 v = make_float4(0.f, 0.f, 0.f, 0.f);
        if (gn < N)
            v = *reinterpret_cast<const float4*>(&g_hact[(size_t)gn * H1F + k4 * 4]);
        float* p = &hs[node * 65 + k4 * 4];
        p[0] = v.x; p[1] = v.y; p[2] = v.z; p[3] = v.w;
    }
    {   // W2: 64x16 = 256 float4
        int k  = t >> 2;
        int c4 = t & 3;
        *reinterpret_cast<float4*>(&ws[k * 16 + c4 * 4]) =
            *reinterpret_cast<const float4*>(&W2[k * 16 + c4 * 4]);
    }
    __syncthreads();

    int j  = t >> 2;          // node within tile
    int c0 = (t & 3) * 4;     // output col group
    unsigned long long acc2[2] = {0ULL, 0ULL};
#pragma unroll
    for (int k = 0; k < 64; k++) {
        unsigned long long xp = pack_ff(hs[j * 65 + k]);
        ulonglong2 wv = *reinterpret_cast<const ulonglong2*>(&ws[k * 16 + c0]);
        fma_f32x2(acc2[0], xp, wv.x);
        fma_f32x2(acc2[1], xp, wv.y);
    }
    float acc[4];
    unpack_ff(acc2[0], acc[0], acc[1]);
    unpack_ff(acc2[1], acc[2], acc[3]);
    int gn = n0 + j;
    if (gn < N)
        *reinterpret_cast<float4*>(&g_h2[(size_t)gn * OUT_CH + c0]) =
            make_float4(acc[0], acc[1], acc[2], acc[3]);
#pragma unroll
    for (int c = 0; c < 4; c++) h2s[j * 17 + c0 + c] = acc[c];
    __syncthreads();
    if (t < 64) {
        int gn2 = n0 + t;
        if (gn2 < N) {
            float es = 0.f, ed = 0.f;
#pragma unroll
            for (int c = 0; c < OUT_CH; c++) {
                float v = h2s[t * 17 + c];
                es = fmaf(v, a2s[c], es);
                ed = fmaf(v, a2d[c], ed);
            }
            g_e2s[gn2] = es;
            g_e2d[gn2] = ed;
        }
    }
}

// ---------------- layer-2 edge aggregation + fused log_softmax ----------------
__global__ void k_edge2(const float* __restrict__ b2, float* __restrict__ out, int N) {
    int w = (blockIdx.x * blockDim.x + threadIdx.x) >> 5;
    if (w >= N) return;
    int lane = threadIdx.x & 31;
    int c = lane & 15;
    int g = lane >> 4;        // two edges per iteration (half-warp each)
    float ed = g_e2d[w];
    int beg = g_off[w], end = g_off[w + 1];
    float acc = 0.f, dn = 0.f;
    for (int i = beg + g; i < end; i += 2) {
        int s = __ldg(&g_csr[i]);
        float t = __ldg(&g_e2s[s]) + ed;
        t = t > 0.f ? t : 0.2f * t;
        float wt = __expf(t);
        acc = fmaf(wt, __ldg(&g_h2[(size_t)s * OUT_CH + c]), acc);
        dn += wt;
    }
    acc += __shfl_xor_sync(0xffffffffu, acc, 16);
    dn  += __shfl_xor_sync(0xffffffffu, dn, 16);
    float v = acc / dn + b2[c];
    // log_softmax over the 16 channels (both half-warps hold identical copies)
    float m = v;
#pragma unroll
    for (int o = 8; o; o >>= 1) m = fmaxf(m, __shfl_xor_sync(0xffffffffu, m, o));
    float S = __expf(v - m);
#pragma unroll
    for (int o = 8; o; o >>= 1) S += __shfl_xor_sync(0xffffffffu, S, o);
    if (lane < 16) out[(size_t)w * OUT_CH + c] = (v - m) - __logf(S);
}

// ---------------- launch ----------------
extern "C" void kernel_launch(void* const* d_in, const int* in_sizes, int n_in,
                              void* d_out, int out_size)
{
    const float* x   = (const float*)d_in[0];
    const int*   ei  = (const int*)  d_in[1];
    const float* W1  = (const float*)d_in[2];
    const float* a1s = (const float*)d_in[3];
    const float* a1d = (const float*)d_in[4];
    const float* b1  = (const float*)d_in[5];
    const float* W2  = (const float*)d_in[6];
    const float* a2s = (const float*)d_in[7];
    const float* a2d = (const float*)d_in[8];
    const float* b2  = (const float*)d_in[9];
    float* out = (float*)d_out;

    int N      = in_sizes[0] / IN_CH;     // 100000
    int E_orig = in_sizes[1] / 2;         // 3200000
    int E_tot  = E_orig + N;

    // gemm1 kept at launch index 3 so the fixed ncu skip-count profiles it.
    k_wsplit <<<16, 256>>>(W1);
    k_zero   <<<(N + 255) / 256, 256>>>(N);
    k_deg    <<<(E_tot + 255) / 256, 256>>>(ei, E_orig, E_tot);
    k_gemm1  <<<(N + 127) / 128, 256, G1_SMEM>>>(x, a1s, a1d, N);
    k_scanA  <<<(N + 1023) / 1024, 1024>>>(N);
    k_scanB  <<<1, 1>>>((N + 1023) / 1024);
    k_scanC  <<<(N + 255) / 256, 256>>>(N);
    k_cursor <<<(N + 255) / 256, 256>>>(N);
    k_scatter<<<(E_tot + 255) / 256, 256>>>(ei, E_orig, E_tot);

    // layer 1 aggregation
    k_edge1<<<(N * 32 + 255) / 256, 256>>>(b1, N);

    // layer 2 + fused log_softmax
    k_gemm2<<<(N + 63) / 64, 256>>>(W2, a2s, a2d, N);
    k_edge2<<<(N * 32 + 255) / 256, 256>>>(b2, out, N);
}

// round 10
// speedup vs baseline: 1.1099x; 1.1099x over previous
#include <cuda_runtime.h>
#include <cuda_bf16.h>
#include <math.h>
#include <stdint.h>

#define N_MAX   100000
#define E_MAX   3300000
#define IN_CH   512
#define H1F     64      // heads1*ch1
#define OUT_CH  16
#define KSTEPS  32      // 512 / 16

// ---------------- device scratch (no allocation allowed) ----------------
__device__ float g_h1  [(size_t)N_MAX * H1F];    // x@W1
__device__ float g_e1s [(size_t)N_MAX * 8];
__device__ float g_e1d [(size_t)N_MAX * 8];
__device__ float g_hact[(size_t)N_MAX * H1F];    // elu(layer1 out)
__device__ float g_h2  [(size_t)N_MAX * OUT_CH]; // hact@W2
__device__ float g_e2s [N_MAX];
__device__ float g_e2d [N_MAX];
__device__ int   g_deg [N_MAX];
__device__ int   g_off [N_MAX + 1];
__device__ int   g_cur [N_MAX];
__device__ int   g_csr [E_MAX];
__device__ int   g_bsum[128];
// W1 pre-packed into mma B-fragment layout (bf16 hi / lo), [ks][nfp][lane]
__device__ uint4 g_wp_h[KSTEPS * 4 * 32];
__device__ uint4 g_wp_l[KSTEPS * 4 * 32];

// ---------------- bf16 split helpers ----------------
// hi = truncate-to-bf16 (top 16 bits); pack pair {f0 -> low half, f1 -> high half}
__device__ __forceinline__ uint32_t hi_pack(float f0, float f1) {
    return __byte_perm(__float_as_uint(f0), __float_as_uint(f1), 0x7632);
}
__device__ __forceinline__ uint32_t lo_pack(float f0, float f1) {
    float l0 = f0 - __uint_as_float(__float_as_uint(f0) & 0xffff0000u);
    float l1 = f1 - __uint_as_float(__float_as_uint(f1) & 0xffff0000u);
    uint32_t r;
    asm("cvt.rn.bf16x2.f32 %0, %1, %2;" : "=r"(r) : "f"(l1), "f"(l0));  // first src -> high half
    return r;
}
__device__ __forceinline__ void mma_bf16(float* d,
                                         uint32_t a0, uint32_t a1, uint32_t a2, uint32_t a3,
                                         uint32_t b0, uint32_t b1) {
    asm("mma.sync.aligned.m16n8k16.row.col.f32.bf16.bf16.f32 "
        "{%0,%1,%2,%3}, {%4,%5,%6,%7}, {%8,%9}, {%0,%1,%2,%3};"
        : "+f"(d[0]), "+f"(d[1]), "+f"(d[2]), "+f"(d[3])
        : "r"(a0), "r"(a1), "r"(a2), "r"(a3), "r"(b0), "r"(b1));
}
__device__ __forceinline__ uint32_t smem_u32(const void* p) {
    uint32_t a;
    asm("{ .reg .u64 t; cvta.to.shared.u64 t, %1; cvt.u32.u64 %0, t; }" : "=r"(a) : "l"(p));
    return a;
}
__device__ __forceinline__ void cpa16(uint32_t dst, const void* src) {
    asm volatile("cp.async.ca.shared.global [%0], [%1], 16;" :: "r"(dst), "l"(src));
}

// ---------------- packed f32x2 helpers (for gemm2) ----------------
__device__ __forceinline__ void fma_f32x2(unsigned long long& acc,
                                          unsigned long long a, unsigned long long b) {
    asm("fma.rn.f32x2 %0, %1, %2, %0;" : "+l"(acc) : "l"(a), "l"(b));
}
__device__ __forceinline__ unsigned long long pack_ff(float v) {
    unsigned long long r;
    asm("mov.b64 %0, {%1, %1};" : "=l"(r) : "f"(v));
    return r;
}
__device__ __forceinline__ void unpack_ff(unsigned long long p, float& lo, float& hi) {
    asm("mov.b64 {%0, %1}, %2;" : "=f"(lo), "=f"(hi) : "l"(p));
}

// ---------------- CSR build ----------------
__global__ void k_zero(int N) {
    int i = blockIdx.x * blockDim.x + threadIdx.x;
    if (i < N) g_deg[i] = 0;
}

__global__ void k_deg(const int* __restrict__ ei, int E_orig, int E_tot) {
    int i = blockIdx.x * blockDim.x + threadIdx.x;
    if (i >= E_tot) return;
    int dst = (i < E_orig) ? ei[E_orig + i] : (i - E_orig);
    atomicAdd(&g_deg[dst], 1);
}

__global__ void k_scanA(int N) {      // grid: ceil(N/1024), block 1024
    __shared__ int s[1024];
    int tid = threadIdx.x;
    int i = blockIdx.x * 1024 + tid;
    int v = (i < N) ? g_deg[i] : 0;
    s[tid] = v;
    __syncthreads();
    for (int o = 1; o < 1024; o <<= 1) {
        int t = (tid >= o) ? s[tid - o] : 0;
        __syncthreads();
        s[tid] += t;
        __syncthreads();
    }
    if (i < N) g_off[i + 1] = s[tid];
    if (tid == 1023) g_bsum[blockIdx.x] = s[1023];
}

__global__ void k_scanB(int nb) {     // <<<1,1>>>
    int run = 0;
    for (int b = 0; b < nb; b++) {
        int t = g_bsum[b];
        g_bsum[b] = run;
        run += t;
    }
}

__global__ void k_scanC(int N) {
    int i = blockIdx.x * blockDim.x + threadIdx.x;
    if (i < N) g_off[i + 1] += g_bsum[i >> 10];
    if (i == 0) g_off[0] = 0;
}

__global__ void k_cursor(int N) {
    int i = blockIdx.x * blockDim.x + threadIdx.x;
    if (i < N) g_cur[i] = g_off[i];
}

__global__ void k_scatter(const int* __restrict__ ei, int E_orig, int E_tot) {
    int i = blockIdx.x * blockDim.x + threadIdx.x;
    if (i >= E_tot) return;
    int src, dst;
    if (i < E_orig) { src = ei[i]; dst = ei[E_orig + i]; }
    else            { src = i - E_orig; dst = src; }
    int p = atomicAdd(&g_cur[dst], 1);
    g_csr[p] = src;
}

// ---------------- W1 pre-pack into B-fragment layout ----------------
// B frag (m16n8k16, col): lane l (g=l>>2, t=l&3): b0={B[2t][g],B[2t+1][g]},
// b1={B[2t+8][g],B[2t+9][g]}. uint4 per (ks,nfp,lane) = {nf0.b0, nf0.b1, nf1.b0, nf1.b1}.
__global__ void k_wsplit(const float* __restrict__ W1) {
    int i = blockIdx.x * blockDim.x + threadIdx.x;   // 0 .. 4095
    if (i >= KSTEPS * 4 * 32) return;
    int ks  = i >> 7;
    int nfp = (i >> 5) & 3;
    int l   = i & 31;
    int g = l >> 2, t = l & 3;
    uint32_t h[4], lo[4];
#pragma unroll
    for (int j = 0; j < 4; j++) {
        int nf  = nfp * 2 + (j >> 1);
        int reg = j & 1;
        int k0  = ks * 16 + 2 * t + reg * 8;
        int col = nf * 8 + g;
        float w0 = W1[k0 * 64 + col];
        float w1 = W1[(k0 + 1) * 64 + col];
        h[j]  = hi_pack(w0, w1);
        lo[j] = lo_pack(w0, w1);
    }
    g_wp_h[i] = make_uint4(h[0], h[1], h[2], h[3]);
    g_wp_l[i] = make_uint4(lo[0], lo[1], lo[2], lo[3]);
}

// ---------------- GEMM1 via mma.sync + PER-WARP cp.async pipeline ----------
// Warp = 16 rows x 64 cols; its x rows are warp-private, so each warp runs a
// private 6-deep cp.async ring (1.25KB/stage). NO __syncthreads in mainloop;
// only cp.async.wait_group + __syncwarp. B-frags from L1-hot pre-packed
// globals. bf16 hi/lo split (3 MMAs per tile).
#define G1_STRIDE 20                      // floats per staged row (16 + 4 pad)
#define G1_NSTG   6
#define G1_WSTG   (16 * G1_STRIDE)        // 320 floats per warp-stage
#define G1_SMEM   (8 * G1_NSTG * G1_WSTG * 4)   // 61440 B per CTA

__global__ __launch_bounds__(256, 3) void k_gemm1(
    const float* __restrict__ x,
    const float* __restrict__ a1s, const float* __restrict__ a1d, int N)
{
    extern __shared__ float sx[];
    int t    = threadIdx.x;
    int wid  = t >> 5;
    int lane = t & 31;
    int g = lane >> 2, q = lane & 3;
    int n0 = blockIdx.x * 128;

    float* wbuf = sx + wid * (G1_NSTG * G1_WSTG);
    const uint32_t wbuf_u = smem_u32(wbuf);

    // producer: lane covers rows (lane>>2) and (lane>>2)+8, chunk col lane&3
    int prow = lane >> 2, pc4 = lane & 3;
    int gnA = n0 + wid * 16 + prow;     if (gnA >= N) gnA = 0;
    int gnB = n0 + wid * 16 + prow + 8; if (gnB >= N) gnB = 0;
    const float* srcA = x + (size_t)gnA * IN_CH + pc4 * 4;
    const float* srcB = x + (size_t)gnB * IN_CH + pc4 * 4;
    uint32_t dstA = wbuf_u + (uint32_t)(prow * G1_STRIDE + pc4 * 4) * 4;
    uint32_t dstB = wbuf_u + (uint32_t)((prow + 8) * G1_STRIDE + pc4 * 4) * 4;

    // consumer offsets within a stage
    int ofA = g * G1_STRIDE + 2 * q;
    int ofB = (g + 8) * G1_STRIDE + 2 * q;

    float acc[8][4];
#pragma unroll
    for (int h = 0; h < 8; h++)
#pragma unroll
        for (int c = 0; c < 4; c++) acc[h][c] = 0.f;

    // prologue: stages 0..4 in flight (5 groups)
#pragma unroll
    for (int s = 0; s < 5; s++) {
        uint32_t bo = (uint32_t)(s * G1_WSTG) * 4;
        cpa16(dstA + bo, srcA + s * 16);
        cpa16(dstB + bo, srcB + s * 16);
        asm volatile("cp.async.commit_group;");
    }

    for (int ks = 0; ks < KSTEPS; ks++) {
        asm volatile("cp.async.wait_group 4;");   // stage ks committed
        __syncwarp();
        {
            int kn = ks + 5;
            if (kn < KSTEPS) {
                uint32_t bo = (uint32_t)(((kn) % G1_NSTG) * G1_WSTG) * 4;
                cpa16(dstA + bo, srcA + kn * 16);
                cpa16(dstB + bo, srcB + kn * 16);
            }
            asm volatile("cp.async.commit_group;");   // empty group past end
        }
        const float* sb = wbuf + (ks % G1_NSTG) * G1_WSTG;
        float2 f0 = *reinterpret_cast<const float2*>(sb + ofA);
        float2 f1 = *reinterpret_cast<const float2*>(sb + ofB);
        float2 f2 = *reinterpret_cast<const float2*>(sb + ofA + 8);
        float2 f3 = *reinterpret_cast<const float2*>(sb + ofB + 8);
        uint32_t ah0 = hi_pack(f0.x, f0.y), ah1 = hi_pack(f1.x, f1.y);
        uint32_t ah2 = hi_pack(f2.x, f2.y), ah3 = hi_pack(f3.x, f3.y);
        uint32_t al0 = lo_pack(f0.x, f0.y), al1 = lo_pack(f1.x, f1.y);
        uint32_t al2 = lo_pack(f2.x, f2.y), al3 = lo_pack(f3.x, f3.y);

        const uint4* wph = &g_wp_h[ks * 128 + lane];
        const uint4* wpl = &g_wp_l[ks * 128 + lane];
#pragma unroll
        for (int nfp = 0; nfp < 4; nfp++) {
            uint4 wh = wph[nfp * 32];
            uint4 wl = wpl[nfp * 32];
            mma_bf16(acc[2 * nfp],     ah0, ah1, ah2, ah3, wh.x, wh.y);
            mma_bf16(acc[2 * nfp],     ah0, ah1, ah2, ah3, wl.x, wl.y);
            mma_bf16(acc[2 * nfp],     al0, al1, al2, al3, wh.x, wh.y);
            mma_bf16(acc[2 * nfp + 1], ah0, ah1, ah2, ah3, wh.z, wh.w);
            mma_bf16(acc[2 * nfp + 1], ah0, ah1, ah2, ah3, wl.z, wl.w);
            mma_bf16(acc[2 * nfp + 1], al0, al1, al2, al3, wh.z, wh.w);
        }
    }

    // epilogue: store h1, compute e1s/e1d per head via quad reduction
    int r0 = n0 + wid * 16 + g;
    int r1 = r0 + 8;
    bool ok0 = (r0 < N), ok1 = (r1 < N);
#pragma unroll
    for (int h = 0; h < 8; h++) {
        if (ok0)
            *reinterpret_cast<float2*>(&g_h1[(size_t)r0 * H1F + h * 8 + 2 * q]) =
                make_float2(acc[h][0], acc[h][1]);
        if (ok1)
            *reinterpret_cast<float2*>(&g_h1[(size_t)r1 * H1F + h * 8 + 2 * q]) =
                make_float2(acc[h][2], acc[h][3]);
        float2 s = *reinterpret_cast<const float2*>(&a1s[h * 8 + 2 * q]);
        float2 d = *reinterpret_cast<const float2*>(&a1d[h * 8 + 2 * q]);
        float es0 = acc[h][0] * s.x + acc[h][1] * s.y;
        float ed0 = acc[h][0] * d.x + acc[h][1] * d.y;
        float es1 = acc[h][2] * s.x + acc[h][3] * s.y;
        float ed1 = acc[h][2] * d.x + acc[h][3] * d.y;
        es0 += __shfl_xor_sync(0xffffffffu, es0, 1);
        es0 += __shfl_xor_sync(0xffffffffu, es0, 2);
        ed0 += __shfl_xor_sync(0xffffffffu, ed0, 1);
        ed0 += __shfl_xor_sync(0xffffffffu, ed0, 2);
        es1 += __shfl_xor_sync(0xffffffffu, es1, 1);
        es1 += __shfl_xor_sync(0xffffffffu, es1, 2);
        ed1 += __shfl_xor_sync(0xffffffffu, ed1, 1);
        ed1 += __shfl_xor_sync(0xffffffffu, ed1, 2);
        if (q == 0) {
            if (ok0) { g_e1s[r0 * 8 + h] = es0; g_e1d[r0 * 8 + h] = ed0; }
            if (ok1) { g_e1s[r1 * 8 + h] = es1; g_e1d[r1 * 8 + h] = ed1; }
        }
    }
}

// ---------------- layer-1 edge aggregation (warp per dst, unroll x2) ----------
// No segment-max needed: logits are O(1), exp() is safe, and
// alpha = exp(l)/sum exp(l) is identical to the max-subtracted form.
__global__ void k_edge1(const float* __restrict__ b1, int N) {
    int w = (blockIdx.x * blockDim.x + threadIdx.x) >> 5;
    if (w >= N) return;
    int lane = threadIdx.x & 31;
    int h0 = lane >> 3;              // feature f0=lane -> head lane/8
    const float ed0 = g_e1d[w * 8 + h0];
    const float ed1 = g_e1d[w * 8 + 4 + h0];   // f1 = lane+32 -> head 4+lane/8
    int beg = g_off[w], end = g_off[w + 1];
    float acc0 = 0.f, acc1 = 0.f, dn0 = 0.f, dn1 = 0.f;
    int i = beg;
    for (; i + 2 <= end; i += 2) {
        int sA = __ldg(&g_csr[i]);
        int sB = __ldg(&g_csr[i + 1]);
        float tA0 = __ldg(&g_e1s[sA * 8 + h0]) + ed0;
        float tA1 = __ldg(&g_e1s[sA * 8 + 4 + h0]) + ed1;
        float tB0 = __ldg(&g_e1s[sB * 8 + h0]) + ed0;
        float tB1 = __ldg(&g_e1s[sB * 8 + 4 + h0]) + ed1;
        float hA0 = __ldg(&g_h1[(size_t)sA * H1F + lane]);
        float hA1 = __ldg(&g_h1[(size_t)sA * H1F + 32 + lane]);
        float hB0 = __ldg(&g_h1[(size_t)sB * H1F + lane]);
        float hB1 = __ldg(&g_h1[(size_t)sB * H1F + 32 + lane]);
        tA0 = tA0 > 0.f ? tA0 : 0.2f * tA0;
        tA1 = tA1 > 0.f ? tA1 : 0.2f * tA1;
        tB0 = tB0 > 0.f ? tB0 : 0.2f * tB0;
        tB1 = tB1 > 0.f ? tB1 : 0.2f * tB1;
        float wA0 = __expf(tA0), wA1 = __expf(tA1);
        float wB0 = __expf(tB0), wB1 = __expf(tB1);
        acc0 = fmaf(wA0, hA0, acc0); dn0 += wA0;
        acc1 = fmaf(wA1, hA1, acc1); dn1 += wA1;
        acc0 = fmaf(wB0, hB0, acc0); dn0 += wB0;
        acc1 = fmaf(wB1, hB1, acc1); dn1 += wB1;
    }
    if (i < end) {
        int s = __ldg(&g_csr[i]);
        float t0 = __ldg(&g_e1s[s * 8 + h0]) + ed0;
        float t1 = __ldg(&g_e1s[s * 8 + 4 + h0]) + ed1;
        t0 = t0 > 0.f ? t0 : 0.2f * t0;
        t1 = t1 > 0.f ? t1 : 0.2f * t1;
        float w0 = __expf(t0);
        float w1 = __expf(t1);
        acc0 = fmaf(w0, __ldg(&g_h1[(size_t)s * H1F + lane]), acc0);
        acc1 = fmaf(w1, __ldg(&g_h1[(size_t)s * H1F + 32 + lane]), acc1);
        dn0 += w0; dn1 += w1;
    }
    float v0 = acc0 / dn0 + b1[lane];
    float v1 = acc1 / dn1 + b1[lane + 32];
    v0 = v0 > 0.f ? v0 : (__expf(v0) - 1.f);   // ELU
    v1 = v1 > 0.f ? v1 : (__expf(v1) - 1.f);
    g_hact[(size_t)w * H1F + lane]      = v0;
    g_hact[(size_t)w * H1F + 32 + lane] = v1;
}

// ---------------- GEMM2: h2 = hact @ W2 (+ e2_src/e2_dst), packed f32x2 -------
__global__ __launch_bounds__(256) void k_gemm2(
    const float* __restrict__ W2, const float* __restrict__ a2s,
    const float* __restrict__ a2d, int N)
{
    __shared__ float hs[64 * 65];
    __shared__ float ws[64 * 16];
    __shared__ float h2s[64 * 17];
    int t  = threadIdx.x;
    int n0 = blockIdx.x * 64;
#pragma unroll
    for (int r = 0; r < 4; r++) {
        int f4   = t + r * 256;
        int node = f4 >> 4;
        int k4   = f4 & 15;
        int gn   = n0 + node;
        float4 v = make_float4(0.f, 0.f, 0.f, 0.f);
        if (gn < N)
            v = *reinterpret_cast<const float4*>(&g_hact[(size_t)gn * H1F + k4 * 4]);
        float* p = &hs[node * 65 + k4 * 4];
        p[0] = v.x; p[1] = v.y; p[2] = v.z; p[3] = v.w;
    }
    {   // W2: 64x16 = 256 float4
        int k  = t >> 2;
        int c4 = t & 3;
        *reinterpret_cast<float4*>(&ws[k * 16 + c4 * 4]) =
            *reinterpret_cast<const float4*>(&W2[k * 16 + c4 * 4]);
    }
    __syncthreads();

    int j  = t >> 2;          // node within tile
    int c0 = (t & 3) * 4;     // output col group
    unsigned long long acc2[2] = {0ULL, 0ULL};
#pragma unroll
    for (int k = 0; k < 64; k++) {
        unsigned long long xp = pack_ff(hs[j * 65 + k]);
        ulonglong2 wv = *reinterpret_cast<const ulonglong2*>(&ws[k * 16 + c0]);
        fma_f32x2(acc2[0], xp, wv.x);
        fma_f32x2(acc2[1], xp, wv.y);
    }
    float acc[4];
    unpack_ff(acc2[0], acc[0], acc[1]);
    unpack_ff(acc2[1], acc[2], acc[3]);
    int gn = n0 + j;
    if (gn < N)
        *reinterpret_cast<float4*>(&g_h2[(size_t)gn * OUT_CH + c0]) =
            make_float4(acc[0], acc[1], acc[2], acc[3]);
#pragma unroll
    for (int c = 0; c < 4; c++) h2s[j * 17 + c0 + c] = acc[c];
    __syncthreads();
    if (t < 64) {
        int gn2 = n0 + t;
        if (gn2 < N) {
            float es = 0.f, ed = 0.f;
#pragma unroll
            for (int c = 0; c < OUT_CH; c++) {
                float v = h2s[t * 17 + c];
                es = fmaf(v, a2s[c], es);
                ed = fmaf(v, a2d[c], ed);
            }
            g_e2s[gn2] = es;
            g_e2d[gn2] = ed;
        }
    }
}

// ---------------- layer-2 edge aggregation + fused log_softmax ----------------
__global__ void k_edge2(const float* __restrict__ b2, float* __restrict__ out, int N) {
    int w = (blockIdx.x * blockDim.x + threadIdx.x) >> 5;
    if (w >= N) return;
    int lane = threadIdx.x & 31;
    int c = lane & 15;
    int g = lane >> 4;        // two edges per iteration (half-warp each)
    float ed = g_e2d[w];
    int beg = g_off[w], end = g_off[w + 1];
    float acc = 0.f, dn = 0.f;
    for (int i = beg + g; i < end; i += 2) {
        int s = __ldg(&g_csr[i]);
        float t = __ldg(&g_e2s[s]) + ed;
        t = t > 0.f ? t : 0.2f * t;
        float wt = __expf(t);
        acc = fmaf(wt, __ldg(&g_h2[(size_t)s * OUT_CH + c]), acc);
        dn += wt;
    }
    acc += __shfl_xor_sync(0xffffffffu, acc, 16);
    dn  += __shfl_xor_sync(0xffffffffu, dn, 16);
    float v = acc / dn + b2[c];
    // log_softmax over the 16 channels (both half-warps hold identical copies)
    float m = v;
#pragma unroll
    for (int o = 8; o; o >>= 1) m = fmaxf(m, __shfl_xor_sync(0xffffffffu, m, o));
    float S = __expf(v - m);
#pragma unroll
    for (int o = 8; o; o >>= 1) S += __shfl_xor_sync(0xffffffffu, S, o);
    if (lane < 16) out[(size_t)w * OUT_CH + c] = (v - m) - __logf(S);
}

// ---------------- launch ----------------
extern "C" void kernel_launch(void* const* d_in, const int* in_sizes, int n_in,
                              void* d_out, int out_size)
{
    const float* x   = (const float*)d_in[0];
    const int*   ei  = (const int*)  d_in[1];
    const float* W1  = (const float*)d_in[2];
    const float* a1s = (const float*)d_in[3];
    const float* a1d = (const float*)d_in[4];
    const float* b1  = (const float*)d_in[5];
    const float* W2  = (const float*)d_in[6];
    const float* a2s = (const float*)d_in[7];
    const float* a2d = (const float*)d_in[8];
    const float* b2  = (const float*)d_in[9];
    float* out = (float*)d_out;

    int N      = in_sizes[0] / IN_CH;     // 100000
    int E_orig = in_sizes[1] / 2;         // 3200000
    int E_tot  = E_orig + N;

    cudaFuncSetAttribute(k_gemm1, cudaFuncAttributeMaxDynamicSharedMemorySize, G1_SMEM);

    // gemm1 kept at launch index 3 so the fixed ncu skip-count profiles it.
    k_wsplit <<<16, 256>>>(W1);
    k_zero   <<<(N + 255) / 256, 256>>>(N);
    k_deg    <<<(E_tot + 255) / 256, 256>>>(ei, E_orig, E_tot);
    k_gemm1  <<<(N + 127) / 128, 256, G1_SMEM>>>(x, a1s, a1d, N);
    k_scanA  <<<(N + 1023) / 1024, 1024>>>(N);
    k_scanB  <<<1, 1>>>((N + 1023) / 1024);
    k_scanC  <<<(N + 255) / 256, 256>>>(N);
    k_cursor <<<(N + 255) / 256, 256>>>(N);
    k_scatter<<<(E_tot + 255) / 256, 256>>>(ei, E_orig, E_tot);

    // layer 1 aggregation
    k_edge1<<<(N * 32 + 255) / 256, 256>>>(b1, N);

    // layer 2 + fused log_softmax
    k_gemm2<<<(N + 63) / 64, 256>>>(W2, a2s, a2d, N);
    k_edge2<<<(N * 32 + 255) / 256, 256>>>(b2, out, N);
}

// round 11
// speedup vs baseline: 1.1317x; 1.0197x over previous
#include <cuda_runtime.h>
#include <cuda_bf16.h>
#include <math.h>
#include <stdint.h>

#define N_MAX   100000
#define E_MAX   3300000
#define IN_CH   512
#define H1F     64      // heads1*ch1
#define OUT_CH  16
#define KSTEPS  32      // 512 / 16

// ---------------- device scratch (no allocation allowed) ----------------
__device__ float g_h1  [(size_t)N_MAX * H1F];    // x@W1
__device__ float g_e1s [(size_t)N_MAX * 8];
__device__ float g_e1d [(size_t)N_MAX * 8];
__device__ float g_hact[(size_t)N_MAX * H1F];    // elu(layer1 out)
__device__ float g_h2  [(size_t)N_MAX * OUT_CH]; // hact@W2
__device__ float g_e2s [N_MAX];
__device__ float g_e2d [N_MAX];
__device__ int   g_deg [N_MAX];
__device__ int   g_off [N_MAX + 1];
__device__ int   g_cur [N_MAX];
__device__ int   g_csr [E_MAX];
__device__ int   g_bsum[128];
// W1 pre-packed into mma B-fragment layout (bf16 hi / lo), [ks][nfp][lane]
__device__ uint4 g_wp_h[KSTEPS * 4 * 32];
__device__ uint4 g_wp_l[KSTEPS * 4 * 32];

// ---------------- bf16 split helpers ----------------
// hi = truncate-to-bf16 (top 16 bits); pack pair {f0 -> low half, f1 -> high half}
__device__ __forceinline__ uint32_t hi_pack(float f0, float f1) {
    return __byte_perm(__float_as_uint(f0), __float_as_uint(f1), 0x7632);
}
__device__ __forceinline__ uint32_t lo_pack(float f0, float f1) {
    float l0 = f0 - __uint_as_float(__float_as_uint(f0) & 0xffff0000u);
    float l1 = f1 - __uint_as_float(__float_as_uint(f1) & 0xffff0000u);
    uint32_t r;
    asm("cvt.rn.bf16x2.f32 %0, %1, %2;" : "=r"(r) : "f"(l1), "f"(l0));  // first src -> high half
    return r;
}
__device__ __forceinline__ void mma_bf16(float* d,
                                         uint32_t a0, uint32_t a1, uint32_t a2, uint32_t a3,
                                         uint32_t b0, uint32_t b1) {
    asm("mma.sync.aligned.m16n8k16.row.col.f32.bf16.bf16.f32 "
        "{%0,%1,%2,%3}, {%4,%5,%6,%7}, {%8,%9}, {%0,%1,%2,%3};"
        : "+f"(d[0]), "+f"(d[1]), "+f"(d[2]), "+f"(d[3])
        : "r"(a0), "r"(a1), "r"(a2), "r"(a3), "r"(b0), "r"(b1));
}
__device__ __forceinline__ uint32_t smem_u32(const void* p) {
    uint32_t a;
    asm("{ .reg .u64 t; cvta.to.shared.u64 t, %1; cvt.u32.u64 %0, t; }" : "=r"(a) : "l"(p));
    return a;
}
__device__ __forceinline__ void cpa16(uint32_t dst, const void* src) {
    asm volatile("cp.async.ca.shared.global [%0], [%1], 16;" :: "r"(dst), "l"(src));
}

// ---------------- packed f32x2 helpers (for gemm2) ----------------
__device__ __forceinline__ void fma_f32x2(unsigned long long& acc,
                                          unsigned long long a, unsigned long long b) {
    asm("fma.rn.f32x2 %0, %1, %2, %0;" : "+l"(acc) : "l"(a), "l"(b));
}
__device__ __forceinline__ unsigned long long pack_ff(float v) {
    unsigned long long r;
    asm("mov.b64 %0, {%1, %1};" : "=l"(r) : "f"(v));
    return r;
}
__device__ __forceinline__ void unpack_ff(unsigned long long p, float& lo, float& hi) {
    asm("mov.b64 {%0, %1}, %2;" : "=f"(lo), "=f"(hi) : "l"(p));
}

// ---------------- CSR build ----------------
__global__ void k_zero(int N) {
    int i = blockIdx.x * blockDim.x + threadIdx.x;
    if (i < N) g_deg[i] = 0;
}

__global__ void k_deg(const int* __restrict__ ei, int E_orig, int E_tot) {
    int i = blockIdx.x * blockDim.x + threadIdx.x;
    if (i >= E_tot) return;
    int dst = (i < E_orig) ? ei[E_orig + i] : (i - E_orig);
    atomicAdd(&g_deg[dst], 1);
}

__global__ void k_scanA(int N) {      // grid: ceil(N/1024), block 1024
    __shared__ int s[1024];
    int tid = threadIdx.x;
    int i = blockIdx.x * 1024 + tid;
    int v = (i < N) ? g_deg[i] : 0;
    s[tid] = v;
    __syncthreads();
    for (int o = 1; o < 1024; o <<= 1) {
        int t = (tid >= o) ? s[tid - o] : 0;
        __syncthreads();
        s[tid] += t;
        __syncthreads();
    }
    if (i < N) g_off[i + 1] = s[tid];
    if (tid == 1023) g_bsum[blockIdx.x] = s[1023];
}

__global__ void k_scanB(int nb) {     // <<<1,128>>> parallel scan of block sums
    __shared__ int s[128];
    int tid = threadIdx.x;
    int v = (tid < nb) ? g_bsum[tid] : 0;
    s[tid] = v;
    __syncthreads();
    for (int o = 1; o < 128; o <<= 1) {
        int t = (tid >= o) ? s[tid - o] : 0;
        __syncthreads();
        s[tid] += t;
        __syncthreads();
    }
    if (tid < nb) g_bsum[tid] = s[tid] - v;   // exclusive prefix
}

__global__ void k_scanC(int N) {      // adds block offsets AND fills cursor
    int i = blockIdx.x * blockDim.x + threadIdx.x;
    if (i < N) {
        int v = g_off[i + 1] + g_bsum[i >> 10];
        g_off[i + 1] = v;
        if (i + 1 < N) g_cur[i + 1] = v;
    }
    if (i == 0) { g_off[0] = 0; g_cur[0] = 0; }
}

__global__ void k_scatter(const int* __restrict__ ei, int E_orig, int E_tot) {
    int i = blockIdx.x * blockDim.x + threadIdx.x;
    if (i >= E_tot) return;
    int src, dst;
    if (i < E_orig) { src = ei[i]; dst = ei[E_orig + i]; }
    else            { src = i - E_orig; dst = src; }
    int p = atomicAdd(&g_cur[dst], 1);
    g_csr[p] = src;
}

// ---------------- W1 pre-pack into B-fragment layout ----------------
// B frag (m16n8k16, col): lane l (g=l>>2, t=l&3): b0={B[2t][g],B[2t+1][g]},
// b1={B[2t+8][g],B[2t+9][g]}. uint4 per (ks,nfp,lane) = {nf0.b0, nf0.b1, nf1.b0, nf1.b1}.
__global__ void k_wsplit(const float* __restrict__ W1) {
    int i = blockIdx.x * blockDim.x + threadIdx.x;   // 0 .. 4095
    if (i >= KSTEPS * 4 * 32) return;
    int ks  = i >> 7;
    int nfp = (i >> 5) & 3;
    int l   = i & 31;
    int g = l >> 2, t = l & 3;
    uint32_t h[4], lo[4];
#pragma unroll
    for (int j = 0; j < 4; j++) {
        int nf  = nfp * 2 + (j >> 1);
        int reg = j & 1;
        int k0  = ks * 16 + 2 * t + reg * 8;
        int col = nf * 8 + g;
        float w0 = W1[k0 * 64 + col];
        float w1 = W1[(k0 + 1) * 64 + col];
        h[j]  = hi_pack(w0, w1);
        lo[j] = lo_pack(w0, w1);
    }
    g_wp_h[i] = make_uint4(h[0], h[1], h[2], h[3]);
    g_wp_l[i] = make_uint4(lo[0], lo[1], lo[2], lo[3]);
}

// ---------------- GEMM1 via mma.sync + PER-WARP cp.async pipeline ----------
// Warp = 16 rows x 64 cols; its x rows are warp-private, so each warp runs a
// private 6-deep cp.async ring (1.25KB/stage). NO __syncthreads in mainloop;
// only cp.async.wait_group + __syncwarp. B-frags from L1-hot pre-packed
// globals. bf16 hi/lo split (3 MMAs per tile).
#define G1_STRIDE 20                      // floats per staged row (16 + 4 pad)
#define G1_NSTG   6
#define G1_WSTG   (16 * G1_STRIDE)        // 320 floats per warp-stage
#define G1_SMEM   (8 * G1_NSTG * G1_WSTG * 4)   // 61440 B per CTA

__global__ __launch_bounds__(256, 3) void k_gemm1(
    const float* __restrict__ x,
    const float* __restrict__ a1s, const float* __restrict__ a1d, int N)
{
    extern __shared__ float sx[];
    int t    = threadIdx.x;
    int wid  = t >> 5;
    int lane = t & 31;
    int g = lane >> 2, q = lane & 3;
    int n0 = blockIdx.x * 128;

    float* wbuf = sx + wid * (G1_NSTG * G1_WSTG);
    const uint32_t wbuf_u = smem_u32(wbuf);

    // producer: lane covers rows (lane>>2) and (lane>>2)+8, chunk col lane&3
    int prow = lane >> 2, pc4 = lane & 3;
    int gnA = n0 + wid * 16 + prow;     if (gnA >= N) gnA = 0;
    int gnB = n0 + wid * 16 + prow + 8; if (gnB >= N) gnB = 0;
    const float* srcA = x + (size_t)gnA * IN_CH + pc4 * 4;
    const float* srcB = x + (size_t)gnB * IN_CH + pc4 * 4;
    uint32_t dstA = wbuf_u + (uint32_t)(prow * G1_STRIDE + pc4 * 4) * 4;
    uint32_t dstB = wbuf_u + (uint32_t)((prow + 8) * G1_STRIDE + pc4 * 4) * 4;

    // consumer offsets within a stage
    int ofA = g * G1_STRIDE + 2 * q;
    int ofB = (g + 8) * G1_STRIDE + 2 * q;

    float acc[8][4];
#pragma unroll
    for (int h = 0; h < 8; h++)
#pragma unroll
        for (int c = 0; c < 4; c++) acc[h][c] = 0.f;

    // prologue: stages 0..4 in flight (5 groups)
#pragma unroll
    for (int s = 0; s < 5; s++) {
        uint32_t bo = (uint32_t)(s * G1_WSTG) * 4;
        cpa16(dstA + bo, srcA + s * 16);
        cpa16(dstB + bo, srcB + s * 16);
        asm volatile("cp.async.commit_group;");
    }

    for (int ks = 0; ks < KSTEPS; ks++) {
        asm volatile("cp.async.wait_group 4;");   // stage ks committed
        __syncwarp();
        {
            int kn = ks + 5;
            if (kn < KSTEPS) {
                uint32_t bo = (uint32_t)(((kn) % G1_NSTG) * G1_WSTG) * 4;
                cpa16(dstA + bo, srcA + kn * 16);
                cpa16(dstB + bo, srcB + kn * 16);
            }
            asm volatile("cp.async.commit_group;");   // empty group past end
        }
        const float* sb = wbuf + (ks % G1_NSTG) * G1_WSTG;
        float2 f0 = *reinterpret_cast<const float2*>(sb + ofA);
        float2 f1 = *reinterpret_cast<const float2*>(sb + ofB);
        float2 f2 = *reinterpret_cast<const float2*>(sb + ofA + 8);
        float2 f3 = *reinterpret_cast<const float2*>(sb + ofB + 8);
        uint32_t ah0 = hi_pack(f0.x, f0.y), ah1 = hi_pack(f1.x, f1.y);
        uint32_t ah2 = hi_pack(f2.x, f2.y), ah3 = hi_pack(f3.x, f3.y);
        uint32_t al0 = lo_pack(f0.x, f0.y), al1 = lo_pack(f1.x, f1.y);
        uint32_t al2 = lo_pack(f2.x, f2.y), al3 = lo_pack(f3.x, f3.y);

        const uint4* wph = &g_wp_h[ks * 128 + lane];
        const uint4* wpl = &g_wp_l[ks * 128 + lane];
#pragma unroll
        for (int nfp = 0; nfp < 4; nfp++) {
            uint4 wh = wph[nfp * 32];
            uint4 wl = wpl[nfp * 32];
            mma_bf16(acc[2 * nfp],     ah0, ah1, ah2, ah3, wh.x, wh.y);
            mma_bf16(acc[2 * nfp],     ah0, ah1, ah2, ah3, wl.x, wl.y);
            mma_bf16(acc[2 * nfp],     al0, al1, al2, al3, wh.x, wh.y);
            mma_bf16(acc[2 * nfp + 1], ah0, ah1, ah2, ah3, wh.z, wh.w);
            mma_bf16(acc[2 * nfp + 1], ah0, ah1, ah2, ah3, wl.z, wl.w);
            mma_bf16(acc[2 * nfp + 1], al0, al1, al2, al3, wh.z, wh.w);
        }
    }

    // epilogue: store h1, compute e1s/e1d per head via quad reduction
    int r0 = n0 + wid * 16 + g;
    int r1 = r0 + 8;
    bool ok0 = (r0 < N), ok1 = (r1 < N);
#pragma unroll
    for (int h = 0; h < 8; h++) {
        if (ok0)
            *reinterpret_cast<float2*>(&g_h1[(size_t)r0 * H1F + h * 8 + 2 * q]) =
                make_float2(acc[h][0], acc[h][1]);
        if (ok1)
            *reinterpret_cast<float2*>(&g_h1[(size_t)r1 * H1F + h * 8 + 2 * q]) =
                make_float2(acc[h][2], acc[h][3]);
        float2 s = *reinterpret_cast<const float2*>(&a1s[h * 8 + 2 * q]);
        float2 d = *reinterpret_cast<const float2*>(&a1d[h * 8 + 2 * q]);
        float es0 = acc[h][0] * s.x + acc[h][1] * s.y;
        float ed0 = acc[h][0] * d.x + acc[h][1] * d.y;
        float es1 = acc[h][2] * s.x + acc[h][3] * s.y;
        float ed1 = acc[h][2] * d.x + acc[h][3] * d.y;
        es0 += __shfl_xor_sync(0xffffffffu, es0, 1);
        es0 += __shfl_xor_sync(0xffffffffu, es0, 2);
        ed0 += __shfl_xor_sync(0xffffffffu, ed0, 1);
        ed0 += __shfl_xor_sync(0xffffffffu, ed0, 2);
        es1 += __shfl_xor_sync(0xffffffffu, es1, 1);
        es1 += __shfl_xor_sync(0xffffffffu, es1, 2);
        ed1 += __shfl_xor_sync(0xffffffffu, ed1, 1);
        ed1 += __shfl_xor_sync(0xffffffffu, ed1, 2);
        if (q == 0) {
            if (ok0) { g_e1s[r0 * 8 + h] = es0; g_e1d[r0 * 8 + h] = ed0; }
            if (ok1) { g_e1s[r1 * 8 + h] = es1; g_e1d[r1 * 8 + h] = ed1; }
        }
    }
}

// ---------------- layer-1 edge aggregation (warp per dst, unroll x4) ----------
// No segment-max needed: logits are O(1), exp() is safe, and
// alpha = exp(l)/sum exp(l) is identical to the max-subtracted form.
__global__ void k_edge1(const float* __restrict__ b1, int N) {
    int w = (blockIdx.x * blockDim.x + threadIdx.x) >> 5;
    if (w >= N) return;
    int lane = threadIdx.x & 31;
    int h0 = lane >> 3;              // feature f0=lane -> head lane/8
    const float ed0 = g_e1d[w * 8 + h0];
    const float ed1 = g_e1d[w * 8 + 4 + h0];   // f1 = lane+32 -> head 4+lane/8
    int beg = g_off[w], end = g_off[w + 1];
    float acc0 = 0.f, acc1 = 0.f, dn0 = 0.f, dn1 = 0.f;
    int i = beg;
    for (; i + 4 <= end; i += 4) {
        int s0 = __ldg(&g_csr[i]);
        int s1 = __ldg(&g_csr[i + 1]);
        int s2 = __ldg(&g_csr[i + 2]);
        int s3 = __ldg(&g_csr[i + 3]);
        float e00 = __ldg(&g_e1s[s0 * 8 + h0]),     e01 = __ldg(&g_e1s[s0 * 8 + 4 + h0]);
        float e10 = __ldg(&g_e1s[s1 * 8 + h0]),     e11 = __ldg(&g_e1s[s1 * 8 + 4 + h0]);
        float e20 = __ldg(&g_e1s[s2 * 8 + h0]),     e21 = __ldg(&g_e1s[s2 * 8 + 4 + h0]);
        float e30 = __ldg(&g_e1s[s3 * 8 + h0]),     e31 = __ldg(&g_e1s[s3 * 8 + 4 + h0]);
        float h00 = __ldg(&g_h1[(size_t)s0 * H1F + lane]);
        float h01 = __ldg(&g_h1[(size_t)s0 * H1F + 32 + lane]);
        float h10 = __ldg(&g_h1[(size_t)s1 * H1F + lane]);
        float h11 = __ldg(&g_h1[(size_t)s1 * H1F + 32 + lane]);
        float h20 = __ldg(&g_h1[(size_t)s2 * H1F + lane]);
        float h21 = __ldg(&g_h1[(size_t)s2 * H1F + 32 + lane]);
        float h30 = __ldg(&g_h1[(size_t)s3 * H1F + lane]);
        float h31 = __ldg(&g_h1[(size_t)s3 * H1F + 32 + lane]);
        float t00 = e00 + ed0, t01 = e01 + ed1;
        float t10 = e10 + ed0, t11 = e11 + ed1;
        float t20 = e20 + ed0, t21 = e21 + ed1;
        float t30 = e30 + ed0, t31 = e31 + ed1;
        t00 = t00 > 0.f ? t00 : 0.2f * t00;  t01 = t01 > 0.f ? t01 : 0.2f * t01;
        t10 = t10 > 0.f ? t10 : 0.2f * t10;  t11 = t11 > 0.f ? t11 : 0.2f * t11;
        t20 = t20 > 0.f ? t20 : 0.2f * t20;  t21 = t21 > 0.f ? t21 : 0.2f * t21;
        t30 = t30 > 0.f ? t30 : 0.2f * t30;  t31 = t31 > 0.f ? t31 : 0.2f * t31;
        float w00 = __expf(t00), w01 = __expf(t01);
        float w10 = __expf(t10), w11 = __expf(t11);
        float w20 = __expf(t20), w21 = __expf(t21);
        float w30 = __expf(t30), w31 = __expf(t31);
        acc0 = fmaf(w00, h00, acc0); dn0 += w00;
        acc1 = fmaf(w01, h01, acc1); dn1 += w01;
        acc0 = fmaf(w10, h10, acc0); dn0 += w10;
        acc1 = fmaf(w11, h11, acc1); dn1 += w11;
        acc0 = fmaf(w20, h20, acc0); dn0 += w20;
        acc1 = fmaf(w21, h21, acc1); dn1 += w21;
        acc0 = fmaf(w30, h30, acc0); dn0 += w30;
        acc1 = fmaf(w31, h31, acc1); dn1 += w31;
    }
    for (; i < end; i++) {
        int s = __ldg(&g_csr[i]);
        float t0 = __ldg(&g_e1s[s * 8 + h0]) + ed0;
        float t1 = __ldg(&g_e1s[s * 8 + 4 + h0]) + ed1;
        t0 = t0 > 0.f ? t0 : 0.2f * t0;
        t1 = t1 > 0.f ? t1 : 0.2f * t1;
        float w0 = __expf(t0);
        float w1 = __expf(t1);
        acc0 = fmaf(w0, __ldg(&g_h1[(size_t)s * H1F + lane]), acc0);
        acc1 = fmaf(w1, __ldg(&g_h1[(size_t)s * H1F + 32 + lane]), acc1);
        dn0 += w0; dn1 += w1;
    }
    float v0 = acc0 / dn0 + b1[lane];
    float v1 = acc1 / dn1 + b1[lane + 32];
    v0 = v0 > 0.f ? v0 : (__expf(v0) - 1.f);   // ELU
    v1 = v1 > 0.f ? v1 : (__expf(v1) - 1.f);
    g_hact[(size_t)w * H1F + lane]      = v0;
    g_hact[(size_t)w * H1F + 32 + lane] = v1;
}

// ---------------- GEMM2: h2 = hact @ W2 (+ e2_src/e2_dst), packed f32x2 -------
__global__ __launch_bounds__(256) void k_gemm2(
    const float* __restrict__ W2, const float* __restrict__ a2s,
    const float* __restrict__ a2d, int N)
{
    __shared__ float hs[64 * 65];
    __shared__ float ws[64 * 16];
    __shared__ float h2s[64 * 17];
    int t  = threadIdx.x;
    int n0 = blockIdx.x * 64;
#pragma unroll
    for (int r = 0; r < 4; r++) {
        int f4   = t + r * 256;
        int node = f4 >> 4;
        int k4   = f4 & 15;
        int gn   = n0 + node;
        float4 v = make_float4(0.f, 0.f, 0.f, 0.f);
        if (gn < N)
            v = *reinterpret_cast<const float4*>(&g_hact[(size_t)gn * H1F + k4 * 4]);
        float* p = &hs[node * 65 + k4 * 4];
        p[0] = v.x; p[1] = v.y; p[2] = v.z; p[3] = v.w;
    }
    {   // W2: 64x16 = 256 float4
        int k  = t >> 2;
        int c4 = t & 3;
        *reinterpret_cast<float4*>(&ws[k * 16 + c4 * 4]) =
            *reinterpret_cast<const float4*>(&W2[k * 16 + c4 * 4]);
    }
    __syncthreads();

    int j  = t >> 2;          // node within tile
    int c0 = (t & 3) * 4;     // output col group
    unsigned long long acc2[2] = {0ULL, 0ULL};
#pragma unroll
    for (int k = 0; k < 64; k++) {
        unsigned long long xp = pack_ff(hs[j * 65 + k]);
        ulonglong2 wv = *reinterpret_cast<const ulonglong2*>(&ws[k * 16 + c0]);
        fma_f32x2(acc2[0], xp, wv.x);
        fma_f32x2(acc2[1], xp, wv.y);
    }
    float acc[4];
    unpack_ff(acc2[0], acc[0], acc[1]);
    unpack_ff(acc2[1], acc[2], acc[3]);
    int gn = n0 + j;
    if (gn < N)
        *reinterpret_cast<float4*>(&g_h2[(size_t)gn * OUT_CH + c0]) =
            make_float4(acc[0], acc[1], acc[2], acc[3]);
#pragma unroll
    for (int c = 0; c < 4; c++) h2s[j * 17 + c0 + c] = acc[c];
    __syncthreads();
    if (t < 64) {
        int gn2 = n0 + t;
        if (gn2 < N) {
            float es = 0.f, ed = 0.f;
#pragma unroll
            for (int c = 0; c < OUT_CH; c++) {
                float v = h2s[t * 17 + c];
                es = fmaf(v, a2s[c], es);
                ed = fmaf(v, a2d[c], ed);
            }
            g_e2s[gn2] = es;
            g_e2d[gn2] = ed;
        }
    }
}

// ---------------- layer-2 edge aggregation + fused log_softmax (unroll x2) ----
__global__ void k_edge2(const float* __restrict__ b2, float* __restrict__ out, int N) {
    int w = (blockIdx.x * blockDim.x + threadIdx.x) >> 5;
    if (w >= N) return;
    int lane = threadIdx.x & 31;
    int c = lane & 15;
    int g = lane >> 4;        // two edge streams (half-warp each)
    float ed = g_e2d[w];
    int beg = g_off[w], end = g_off[w + 1];
    float acc = 0.f, dn = 0.f;
    int i = beg + g;
    for (; i + 2 < end; i += 4) {
        int sA = __ldg(&g_csr[i]);
        int sB = __ldg(&g_csr[i + 2]);
        float tA = __ldg(&g_e2s[sA]) + ed;
        float tB = __ldg(&g_e2s[sB]) + ed;
        float hA = __ldg(&g_h2[(size_t)sA * OUT_CH + c]);
        float hB = __ldg(&g_h2[(size_t)sB * OUT_CH + c]);
        tA = tA > 0.f ? tA : 0.2f * tA;
        tB = tB > 0.f ? tB : 0.2f * tB;
        float wA = __expf(tA);
        float wB = __expf(tB);
        acc = fmaf(wA, hA, acc); dn += wA;
        acc = fmaf(wB, hB, acc); dn += wB;
    }
    if (i < end) {
        int s = __ldg(&g_csr[i]);
        float t = __ldg(&g_e2s[s]) + ed;
        t = t > 0.f ? t : 0.2f * t;
        float wt = __expf(t);
        acc = fmaf(wt, __ldg(&g_h2[(size_t)s * OUT_CH + c]), acc);
        dn += wt;
    }
    acc += __shfl_xor_sync(0xffffffffu, acc, 16);
    dn  += __shfl_xor_sync(0xffffffffu, dn, 16);
    float v = acc / dn + b2[c];
    // log_softmax over the 16 channels (both half-warps hold identical copies)
    float m = v;
#pragma unroll
    for (int o = 8; o; o >>= 1) m = fmaxf(m, __shfl_xor_sync(0xffffffffu, m, o));
    float S = __expf(v - m);
#pragma unroll
    for (int o = 8; o; o >>= 1) S += __shfl_xor_sync(0xffffffffu, S, o);
    if (lane < 16) out[(size_t)w * OUT_CH + c] = (v - m) - __logf(S);
}

// ---------------- launch ----------------
extern "C" void kernel_launch(void* const* d_in, const int* in_sizes, int n_in,
                              void* d_out, int out_size)
{
    const float* x   = (const float*)d_in[0];
    const int*   ei  = (const int*)  d_in[1];
    const float* W1  = (const float*)d_in[2];
    const float* a1s = (const float*)d_in[3];
    const float* a1d = (const float*)d_in[4];
    const float* b1  = (const float*)d_in[5];
    const float* W2  = (const float*)d_in[6];
    const float* a2s = (const float*)d_in[7];
    const float* a2d = (const float*)d_in[8];
    const float* b2  = (const float*)d_in[9];
    float* out = (float*)d_out;

    int N      = in_sizes[0] / IN_CH;     // 100000
    int E_orig = in_sizes[1] / 2;         // 3200000
    int E_tot  = E_orig + N;

    cudaFuncSetAttribute(k_gemm1, cudaFuncAttributeMaxDynamicSharedMemorySize, G1_SMEM);

    // gemm1 kept at launch index 3 so the fixed ncu skip-count profiles it.
    k_wsplit <<<16, 256>>>(W1);
    k_zero   <<<(N + 255) / 256, 256>>>(N);
    k_deg    <<<(E_tot + 255) / 256, 256>>>(ei, E_orig, E_tot);
    k_gemm1  <<<(N + 127) / 128, 256, G1_SMEM>>>(x, a1s, a1d, N);
    k_scanA  <<<(N + 1023) / 1024, 1024>>>(N);
    k_scanB  <<<1, 128>>>((N + 1023) / 1024);
    k_scanC  <<<(N + 255) / 256, 256>>>(N);
    k_scatter<<<(E_tot + 255) / 256, 256>>>(ei, E_orig, E_tot);

    // layer 1 aggregation
    k_edge1<<<(N * 32 + 255) / 256, 256>>>(b1, N);

    // layer 2 + fused log_softmax
    k_gemm2<<<(N + 63) / 64, 256>>>(W2, a2s, a2d, N);
    k_edge2<<<(N * 32 + 255) / 256, 256>>>(b2, out, N);
}

// round 14
// speedup vs baseline: 1.3188x; 1.1653x over previous
#include <cuda_runtime.h>
#include <cuda_bf16.h>
#include <cuda_fp16.h>
#include <math.h>
#include <stdint.h>

#define N_MAX   100000
#define E_MAX   3300000
#define IN_CH   512
#define H1F     64      // heads1*ch1
#define OUT_CH  16
#define KSTEPS  32      // 512 / 16

// ---------------- device scratch (no allocation allowed) ----------------
__device__ __half2 g_h1h[(size_t)N_MAX * 32];    // x@W1 in fp16 pairs (edge1-only)
__device__ float g_e1s [(size_t)N_MAX * 8];
__device__ float g_e1d [(size_t)N_MAX * 8];
__device__ float g_hact[(size_t)N_MAX * H1F];    // elu(layer1 out)
__device__ float g_h2  [(size_t)N_MAX * OUT_CH]; // hact@W2
__device__ float g_e2s [N_MAX];
__device__ float g_e2d [N_MAX];
__device__ int   g_deg [N_MAX];
__device__ int   g_off [N_MAX + 1];
__device__ int   g_cur [N_MAX];
__device__ int   g_csr [E_MAX];
__device__ int   g_bsum[128];
// W1 pre-packed into mma B-fragment layout (bf16 hi / lo), [ks][nfp][lane]
__device__ uint4 g_wp_h[KSTEPS * 4 * 32];
__device__ uint4 g_wp_l[KSTEPS * 4 * 32];

// ---------------- bf16 split helpers ----------------
// hi = truncate-to-bf16 (top 16 bits); pack pair {f0 -> low half, f1 -> high half}
__device__ __forceinline__ uint32_t hi_pack(float f0, float f1) {
    return __byte_perm(__float_as_uint(f0), __float_as_uint(f1), 0x7632);
}
__device__ __forceinline__ uint32_t lo_pack(float f0, float f1) {
    float l0 = f0 - __uint_as_float(__float_as_uint(f0) & 0xffff0000u);
    float l1 = f1 - __uint_as_float(__float_as_uint(f1) & 0xffff0000u);
    uint32_t r;
    asm("cvt.rn.bf16x2.f32 %0, %1, %2;" : "=r"(r) : "f"(l1), "f"(l0));  // first src -> high half
    return r;
}
__device__ __forceinline__ void mma_bf16(float* d,
                                         uint32_t a0, uint32_t a1, uint32_t a2, uint32_t a3,
                                         uint32_t b0, uint32_t b1) {
    asm("mma.sync.aligned.m16n8k16.row.col.f32.bf16.bf16.f32 "
        "{%0,%1,%2,%3}, {%4,%5,%6,%7}, {%8,%9}, {%0,%1,%2,%3};"
        : "+f"(d[0]), "+f"(d[1]), "+f"(d[2]), "+f"(d[3])
        : "r"(a0), "r"(a1), "r"(a2), "r"(a3), "r"(b0), "r"(b1));
}
__device__ __forceinline__ uint32_t smem_u32(const void* p) {
    uint32_t a;
    asm("{ .reg .u64 t; cvta.to.shared.u64 t, %1; cvt.u32.u64 %0, t; }" : "=r"(a) : "l"(p));
    return a;
}
__device__ __forceinline__ void cpa16(uint32_t dst, const void* src) {
    asm volatile("cp.async.ca.shared.global [%0], [%1], 16;" :: "r"(dst), "l"(src));
}

// ---------------- packed f32x2 helpers (for gemm2) ----------------
__device__ __forceinline__ void fma_f32x2(unsigned long long& acc,
                                          unsigned long long a, unsigned long long b) {
    asm("fma.rn.f32x2 %0, %1, %2, %0;" : "+l"(acc) : "l"(a), "l"(b));
}
__device__ __forceinline__ unsigned long long pack_ff(float v) {
    unsigned long long r;
    asm("mov.b64 %0, {%1, %1};" : "=l"(r) : "f"(v));
    return r;
}
__device__ __forceinline__ void unpack_ff(unsigned long long p, float& lo, float& hi) {
    asm("mov.b64 {%0, %1}, %2;" : "=f"(lo), "=f"(hi) : "l"(p));
}

// ---------------- CSR build ----------------
__global__ void k_zero(int N) {
    int i = blockIdx.x * blockDim.x + threadIdx.x;
    if (i < N) g_deg[i] = 0;
}

__global__ void k_deg(const int* __restrict__ ei, int E_orig, int E_tot) {
    int i = blockIdx.x * blockDim.x + threadIdx.x;
    if (i >= E_tot) return;
    int dst = (i < E_orig) ? ei[E_orig + i] : (i - E_orig);
    atomicAdd(&g_deg[dst], 1);
}

__global__ void k_scanA(int N) {      // grid: ceil(N/1024), block 1024
    __shared__ int s[1024];
    int tid = threadIdx.x;
    int i = blockIdx.x * 1024 + tid;
    int v = (i < N) ? g_deg[i] : 0;
    s[tid] = v;
    __syncthreads();
    for (int o = 1; o < 1024; o <<= 1) {
        int t = (tid >= o) ? s[tid - o] : 0;
        __syncthreads();
        s[tid] += t;
        __syncthreads();
    }
    if (i < N) g_off[i + 1] = s[tid];
    if (tid == 1023) g_bsum[blockIdx.x] = s[1023];
}

__global__ void k_scanB(int nb) {     // <<<1,128>>> parallel scan of block sums
    __shared__ int s[128];
    int tid = threadIdx.x;
    int v = (tid < nb) ? g_bsum[tid] : 0;
    s[tid] = v;
    __syncthreads();
    for (int o = 1; o < 128; o <<= 1) {
        int t = (tid >= o) ? s[tid - o] : 0;
        __syncthreads();
        s[tid] += t;
        __syncthreads();
    }
    if (tid < nb) g_bsum[tid] = s[tid] - v;   // exclusive prefix
}

__global__ void k_scanC(int N) {      // adds block offsets AND fills cursor
    int i = blockIdx.x * blockDim.x + threadIdx.x;
    if (i < N) {
        int v = g_off[i + 1] + g_bsum[i >> 10];
        g_off[i + 1] = v;
        if (i + 1 < N) g_cur[i + 1] = v;
    }
    if (i == 0) { g_off[0] = 0; g_cur[0] = 0; }
}

__global__ void k_scatter(const int* __restrict__ ei, int E_orig, int E_tot) {
    int i = blockIdx.x * blockDim.x + threadIdx.x;
    if (i >= E_tot) return;
    int src, dst;
    if (i < E_orig) { src = ei[i]; dst = ei[E_orig + i]; }
    else            { src = i - E_orig; dst = src; }
    int p = atomicAdd(&g_cur[dst], 1);
    g_csr[p] = src;
}

// ---------------- W1 pre-pack into B-fragment layout ----------------
// B frag (m16n8k16, col): lane l (g=l>>2, t=l&3): b0={B[2t][g],B[2t+1][g]},
// b1={B[2t+8][g],B[2t+9][g]}. uint4 per (ks,nfp,lane) = {nf0.b0, nf0.b1, nf1.b0, nf1.b1}.
__global__ void k_wsplit(const float* __restrict__ W1) {
    int i = blockIdx.x * blockDim.x + threadIdx.x;   // 0 .. 4095
    if (i >= KSTEPS * 4 * 32) return;
    int ks  = i >> 7;
    int nfp = (i >> 5) & 3;
    int l   = i & 31;
    int g = l >> 2, t = l & 3;
    uint32_t h[4], lo[4];
#pragma unroll
    for (int j = 0; j < 4; j++) {
        int nf  = nfp * 2 + (j >> 1);
        int reg = j & 1;
        int k0  = ks * 16 + 2 * t + reg * 8;
        int col = nf * 8 + g;
        float w0 = W1[k0 * 64 + col];
        float w1 = W1[(k0 + 1) * 64 + col];
        h[j]  = hi_pack(w0, w1);
        lo[j] = lo_pack(w0, w1);
    }
    g_wp_h[i] = make_uint4(h[0], h[1], h[2], h[3]);
    g_wp_l[i] = make_uint4(lo[0], lo[1], lo[2], lo[3]);
}

// ---------------- GEMM1 via mma.sync + PER-WARP cp.async pipeline ----------
// Warp = 16 rows x 64 cols; its x rows are warp-private, so each warp runs a
// private 6-deep cp.async ring (1.25KB/stage). NO __syncthreads in mainloop;
// only cp.async.wait_group + __syncwarp. B-frags from L1-hot pre-packed
// globals. bf16 hi/lo split (3 MMAs per tile).
#define G1_STRIDE 20                      // floats per staged row (16 + 4 pad)
#define G1_NSTG   6
#define G1_WSTG   (16 * G1_STRIDE)        // 320 floats per warp-stage
#define G1_SMEM   (8 * G1_NSTG * G1_WSTG * 4)   // 61440 B per CTA

__global__ __launch_bounds__(256, 3) void k_gemm1(
    const float* __restrict__ x,
    const float* __restrict__ a1s, const float* __restrict__ a1d, int N)
{
    extern __shared__ float sx[];
    int t    = threadIdx.x;
    int wid  = t >> 5;
    int lane = t & 31;
    int g = lane >> 2, q = lane & 3;
    int n0 = blockIdx.x * 128;

    float* wbuf = sx + wid * (G1_NSTG * G1_WSTG);
    const uint32_t wbuf_u = smem_u32(wbuf);

    // producer: lane covers rows (lane>>2) and (lane>>2)+8, chunk col lane&3
    int prow = lane >> 2, pc4 = lane & 3;
    int gnA = n0 + wid * 16 + prow;     if (gnA >= N) gnA = 0;
    int gnB = n0 + wid * 16 + prow + 8; if (gnB >= N) gnB = 0;
    const float* srcA = x + (size_t)gnA * IN_CH + pc4 * 4;
    const float* srcB = x + (size_t)gnB * IN_CH + pc4 * 4;
    uint32_t dstA = wbuf_u + (uint32_t)(prow * G1_STRIDE + pc4 * 4) * 4;
    uint32_t dstB = wbuf_u + (uint32_t)((prow + 8) * G1_STRIDE + pc4 * 4) * 4;

    // consumer offsets within a stage
    int ofA = g * G1_STRIDE + 2 * q;
    int ofB = (g + 8) * G1_STRIDE + 2 * q;

    float acc[8][4];
#pragma unroll
    for (int h = 0; h < 8; h++)
#pragma unroll
        for (int c = 0; c < 4; c++) acc[h][c] = 0.f;

    // prologue: stages 0..4 in flight (5 groups)
#pragma unroll
    for (int s = 0; s < 5; s++) {
        uint32_t bo = (uint32_t)(s * G1_WSTG) * 4;
        cpa16(dstA + bo, srcA + s * 16);
        cpa16(dstB + bo, srcB + s * 16);
        asm volatile("cp.async.commit_group;");
    }

    for (int ks = 0; ks < KSTEPS; ks++) {
        asm volatile("cp.async.wait_group 4;");   // stage ks committed
        __syncwarp();
        {
            int kn = ks + 5;
            if (kn < KSTEPS) {
                uint32_t bo = (uint32_t)(((kn) % G1_NSTG) * G1_WSTG) * 4;
                cpa16(dstA + bo, srcA + kn * 16);
                cpa16(dstB + bo, srcB + kn * 16);
            }
            asm volatile("cp.async.commit_group;");   // empty group past end
        }
        const float* sb = wbuf + (ks % G1_NSTG) * G1_WSTG;
        float2 f0 = *reinterpret_cast<const float2*>(sb + ofA);
        float2 f1 = *reinterpret_cast<const float2*>(sb + ofB);
        float2 f2 = *reinterpret_cast<const float2*>(sb + ofA + 8);
        float2 f3 = *reinterpret_cast<const float2*>(sb + ofB + 8);
        uint32_t ah0 = hi_pack(f0.x, f0.y), ah1 = hi_pack(f1.x, f1.y);
        uint32_t ah2 = hi_pack(f2.x, f2.y), ah3 = hi_pack(f3.x, f3.y);
        uint32_t al0 = lo_pack(f0.x, f0.y), al1 = lo_pack(f1.x, f1.y);
        uint32_t al2 = lo_pack(f2.x, f2.y), al3 = lo_pack(f3.x, f3.y);

        const uint4* wph = &g_wp_h[ks * 128 + lane];
        const uint4* wpl = &g_wp_l[ks * 128 + lane];
#pragma unroll
        for (int nfp = 0; nfp < 4; nfp++) {
            uint4 wh = wph[nfp * 32];
            uint4 wl = wpl[nfp * 32];
            mma_bf16(acc[2 * nfp],     ah0, ah1, ah2, ah3, wh.x, wh.y);
            mma_bf16(acc[2 * nfp],     ah0, ah1, ah2, ah3, wl.x, wl.y);
            mma_bf16(acc[2 * nfp],     al0, al1, al2, al3, wh.x, wh.y);
            mma_bf16(acc[2 * nfp + 1], ah0, ah1, ah2, ah3, wh.z, wh.w);
            mma_bf16(acc[2 * nfp + 1], ah0, ah1, ah2, ah3, wl.z, wl.w);
            mma_bf16(acc[2 * nfp + 1], al0, al1, al2, al3, wh.z, wh.w);
        }
    }

    // epilogue: store h1 (fp16 pairs), compute e1s/e1d per head via quad reduce
    int r0 = n0 + wid * 16 + g;
    int r1 = r0 + 8;
    bool ok0 = (r0 < N), ok1 = (r1 < N);
#pragma unroll
    for (int h = 0; h < 8; h++) {
        if (ok0)
            g_h1h[(size_t)r0 * 32 + h * 4 + q] = __floats2half2_rn(acc[h][0], acc[h][1]);
        if (ok1)
            g_h1h[(size_t)r1 * 32 + h * 4 + q] = __floats2half2_rn(acc[h][2], acc[h][3]);
        float2 s = *reinterpret_cast<const float2*>(&a1s[h * 8 + 2 * q]);
        float2 d = *reinterpret_cast<const float2*>(&a1d[h * 8 + 2 * q]);
        float es0 = acc[h][0] * s.x + acc[h][1] * s.y;
        float ed0 = acc[h][0] * d.x + acc[h][1] * d.y;
        float es1 = acc[h][2] * s.x + acc[h][3] * s.y;
        float ed1 = acc[h][2] * d.x + acc[h][3] * d.y;
        es0 += __shfl_xor_sync(0xffffffffu, es0, 1);
        es0 += __shfl_xor_sync(0xffffffffu, es0, 2);
        ed0 += __shfl_xor_sync(0xffffffffu, ed0, 1);
        ed0 += __shfl_xor_sync(0xffffffffu, ed0, 2);
        es1 += __shfl_xor_sync(0xffffffffu, es1, 1);
        es1 += __shfl_xor_sync(0xffffffffu, es1, 2);
        ed1 += __shfl_xor_sync(0xffffffffu, ed1, 1);
        ed1 += __shfl_xor_sync(0xffffffffu, ed1, 2);
        if (q == 0) {
            if (ok0) { g_e1s[r0 * 8 + h] = es0; g_e1d[r0 * 8 + h] = ed0; }
            if (ok1) { g_e1s[r1 * 8 + h] = es1; g_e1d[r1 * 8 + h] = ed1; }
        }
    }
}

// ---------------- layer-1 edge aggregation (warp per dst, fp16 h1) ----------
// Lane l handles features {2l, 2l+1} (same head l>>2): one half2 load, one
// e-stream, one expf per edge per lane. No segment-max needed: logits are
// O(1), exp() safe; alpha = exp(l)/sum exp(l) identical to max-subtracted.
__global__ void k_edge1(const float* __restrict__ b1, int N) {
    int w = (blockIdx.x * blockDim.x + threadIdx.x) >> 5;
    if (w >= N) return;
    int lane = threadIdx.x & 31;
    int h = lane >> 2;               // head for both features
    const float ed = g_e1d[w * 8 + h];
    int beg = g_off[w], end = g_off[w + 1];
    float acc0 = 0.f, acc1 = 0.f, dn = 0.f;
    int i = beg;
    for (; i + 4 <= end; i += 4) {
        int s0 = __ldg(&g_csr[i]);
        int s1 = __ldg(&g_csr[i + 1]);
        int s2 = __ldg(&g_csr[i + 2]);
        int s3 = __ldg(&g_csr[i + 3]);
        float e0 = __ldg(&g_e1s[s0 * 8 + h]);
        float e1 = __ldg(&g_e1s[s1 * 8 + h]);
        float e2 = __ldg(&g_e1s[s2 * 8 + h]);
        float e3 = __ldg(&g_e1s[s3 * 8 + h]);
        __half2 p0 = __ldg(&g_h1h[(size_t)s0 * 32 + lane]);
        __half2 p1 = __ldg(&g_h1h[(size_t)s1 * 32 + lane]);
        __half2 p2 = __ldg(&g_h1h[(size_t)s2 * 32 + lane]);
        __half2 p3 = __ldg(&g_h1h[(size_t)s3 * 32 + lane]);
        float t0 = e0 + ed, t1 = e1 + ed, t2 = e2 + ed, t3 = e3 + ed;
        t0 = t0 > 0.f ? t0 : 0.2f * t0;
        t1 = t1 > 0.f ? t1 : 0.2f * t1;
        t2 = t2 > 0.f ? t2 : 0.2f * t2;
        t3 = t3 > 0.f ? t3 : 0.2f * t3;
        float w0 = __expf(t0), w1 = __expf(t1), w2 = __expf(t2), w3 = __expf(t3);
        float2 v0 = __half22float2(p0);
        float2 v1 = __half22float2(p1);
        float2 v2 = __half22float2(p2);
        float2 v3 = __half22float2(p3);
        acc0 = fmaf(w0, v0.x, acc0); acc1 = fmaf(w0, v0.y, acc1); dn += w0;
        acc0 = fmaf(w1, v1.x, acc0); acc1 = fmaf(w1, v1.y, acc1); dn += w1;
        acc0 = fmaf(w2, v2.x, acc0); acc1 = fmaf(w2, v2.y, acc1); dn += w2;
        acc0 = fmaf(w3, v3.x, acc0); acc1 = fmaf(w3, v3.y, acc1); dn += w3;
    }
    for (; i < end; i++) {
        int s = __ldg(&g_csr[i]);
        float t = __ldg(&g_e1s[s * 8 + h]) + ed;
        t = t > 0.f ? t : 0.2f * t;
        float wt = __expf(t);
        float2 v = __half22float2(__ldg(&g_h1h[(size_t)s * 32 + lane]));
        acc0 = fmaf(wt, v.x, acc0);
        acc1 = fmaf(wt, v.y, acc1);
        dn += wt;
    }
    float2 bb = *reinterpret_cast<const float2*>(&b1[2 * lane]);
    float v0 = acc0 / dn + bb.x;
    float v1 = acc1 / dn + bb.y;
    v0 = v0 > 0.f ? v0 : (__expf(v0) - 1.f);   // ELU
    v1 = v1 > 0.f ? v1 : (__expf(v1) - 1.f);
    *reinterpret_cast<float2*>(&g_hact[(size_t)w * H1F + 2 * lane]) =
        make_float2(v0, v1);
}

// ---------------- GEMM2: h2 = hact @ W2 (+ e2_src/e2_dst), packed f32x2 -------
__global__ __launch_bounds__(256) void k_gemm2(
    const float* __restrict__ W2, const float* __restrict__ a2s,
    const float* __restrict__ a2d, int N)
{
    __shared__ float hs[64 * 65];
    __shared__ float ws[64 * 16];
    __shared__ float h2s[64 * 17];
    int t  = threadIdx.x;
    int n0 = blockIdx.x * 64;
#pragma unroll
    for (int r = 0; r < 4; r++) {
        int f4   = t + r * 256;
        int node = f4 >> 4;
        int k4   = f4 & 15;
        int gn   = n0 + node;
        float4 v = make_float4(0.f, 0.f, 0.f, 0.f);
        if (gn < N)
            v = *reinterpret_cast<const float4*>(&g_hact[(size_t)gn * H1F + k4 * 4]);
        float* p = &hs[node * 65 + k4 * 4];
        p[0] = v.x; p[1] = v.y; p[2] = v.z; p[3] = v.w;
    }
    {   // W2: 64x16 = 256 float4
        int k  = t >> 2;
        int c4 = t & 3;
        *reinterpret_cast<float4*>(&ws[k * 16 + c4 * 4]) =
            *reinterpret_cast<const float4*>(&W2[k * 16 + c4 * 4]);
    }
    __syncthreads();

    int j  = t >> 2;          // node within tile
    int c0 = (t & 3) * 4;     // output col group
    unsigned long long acc2[2] = {0ULL, 0ULL};
#pragma unroll
    for (int k = 0; k < 64; k++) {
        unsigned long long xp = pack_ff(hs[j * 65 + k]);
        ulonglong2 wv = *reinterpret_cast<const ulonglong2*>(&ws[k * 16 + c0]);
        fma_f32x2(acc2[0], xp, wv.x);
        fma_f32x2(acc2[1], xp, wv.y);
    }
    float acc[4];
    unpack_ff(acc2[0], acc[0], acc[1]);
    unpack_ff(acc2[1], acc[2], acc[3]);
    int gn = n0 + j;
    if (gn < N)
        *reinterpret_cast<float4*>(&g_h2[(size_t)gn * OUT_CH + c0]) =
            make_float4(acc[0], acc[1], acc[2], acc[3]);
#pragma unroll
    for (int c = 0; c < 4; c++) h2s[j * 17 + c0 + c] = acc[c];
    __syncthreads();
    if (t < 64) {
        int gn2 = n0 + t;
        if (gn2 < N) {
            float es = 0.f, ed = 0.f;
#pragma unroll
            for (int c = 0; c < OUT_CH; c++) {
                float v = h2s[t * 17 + c];
                es = fmaf(v, a2s[c], es);
                ed = fmaf(v, a2d[c], ed);
            }
            g_e2s[gn2] = es;
            g_e2d[gn2] = ed;
        }
    }
}

// ---------------- layer-2 edge aggregation + fused log_softmax (unroll x2) ----
__global__ void k_edge2(const float* __restrict__ b2, float* __restrict__ out, int N) {
    int w = (blockIdx.x * blockDim.x + threadIdx.x) >> 5;
    if (w >= N) return;
    int lane = threadIdx.x & 31;
    int c = lane & 15;
    int g = lane >> 4;        // two edge streams (half-warp each)
    float ed = g_e2d[w];
    int beg = g_off[w], end = g_off[w + 1];
    float acc = 0.f, dn = 0.f;
    int i = beg + g;
    for (; i + 2 < end; i += 4) {
        int sA = __ldg(&g_csr[i]);
        int sB = __ldg(&g_csr[i + 2]);
        float tA = __ldg(&g_e2s[sA]) + ed;
        float tB = __ldg(&g_e2s[sB]) + ed;
        float hA = __ldg(&g_h2[(size_t)sA * OUT_CH + c]);
        float hB = __ldg(&g_h2[(size_t)sB * OUT_CH + c]);
        tA = tA > 0.f ? tA : 0.2f * tA;
        tB = tB > 0.f ? tB : 0.2f * tB;
        float wA = __expf(tA);
        float wB = __expf(tB);
        acc = fmaf(wA, hA, acc); dn += wA;
        acc = fmaf(wB, hB, acc); dn += wB;
    }
    if (i < end) {
        int s = __ldg(&g_csr[i]);
        float t = __ldg(&g_e2s[s]) + ed;
        t = t > 0.f ? t : 0.2f * t;
        float wt = __expf(t);
        acc = fmaf(wt, __ldg(&g_h2[(size_t)s * OUT_CH + c]), acc);
        dn += wt;
    }
    acc += __shfl_xor_sync(0xffffffffu, acc, 16);
    dn  += __shfl_xor_sync(0xffffffffu, dn, 16);
    float v = acc / dn + b2[c];
    // log_softmax over the 16 channels (both half-warps hold identical copies)
    float m = v;
#pragma unroll
    for (int o = 8; o; o >>= 1) m = fmaxf(m, __shfl_xor_sync(0xffffffffu, m, o));
    float S = __expf(v - m);
#pragma unroll
    for (int o = 8; o; o >>= 1) S += __shfl_xor_sync(0xffffffffu, S, o);
    if (lane < 16) out[(size_t)w * OUT_CH + c] = (v - m) - __logf(S);
}

// ---------------- launch ----------------
extern "C" void kernel_launch(void* const* d_in, const int* in_sizes, int n_in,
                              void* d_out, int out_size)
{
    const float* x   = (const float*)d_in[0];
    const int*   ei  = (const int*)  d_in[1];
    const float* W1  = (const float*)d_in[2];
    const float* a1s = (const float*)d_in[3];
    const float* a1d = (const float*)d_in[4];
    const float* b1  = (const float*)d_in[5];
    const float* W2  = (const float*)d_in[6];
    const float* a2s = (const float*)d_in[7];
    const float* a2d = (const float*)d_in[8];
    const float* b2  = (const float*)d_in[9];
    float* out = (float*)d_out;

    int N      = in_sizes[0] / IN_CH;     // 100000
    int E_orig = in_sizes[1] / 2;         // 3200000
    int E_tot  = E_orig + N;

    cudaFuncSetAttribute(k_gemm1, cudaFuncAttributeMaxDynamicSharedMemorySize, G1_SMEM);

    // gemm1 kept at launch index 3 so the fixed ncu skip-count profiles it.
    k_wsplit <<<16, 256>>>(W1);
    k_zero   <<<(N + 255) / 256, 256>>>(N);
    k_deg    <<<(E_tot + 255) / 256, 256>>>(ei, E_orig, E_tot);
    k_gemm1  <<<(N + 127) / 128, 256, G1_SMEM>>>(x, a1s, a1d, N);
    k_scanA  <<<(N + 1023) / 1024, 1024>>>(N);
    k_scanB  <<<1, 128>>>((N + 1023) / 1024);
    k_scanC  <<<(N + 255) / 256, 256>>>(N);
    k_scatter<<<(E_tot + 255) / 256, 256>>>(ei, E_orig, E_tot);

    // layer 1 aggregation
    k_edge1<<<(N * 32 + 255) / 256, 256>>>(b1, N);

    // layer 2 + fused log_softmax
    k_gemm2<<<(N + 63) / 64, 256>>>(W2, a2s, a2d, N);
    k_edge2<<<(N * 32 + 255) / 256, 256>>>(b2, out, N);
}

// round 16
// speedup vs baseline: 1.3460x; 1.0206x over previous
#include <cuda_runtime.h>
#include <cuda_bf16.h>
#include <cuda_fp16.h>
#include <math.h>
#include <stdint.h>

#define N_MAX   100000
#define E_MAX   3300000
#define IN_CH   512
#define H1F     64      // heads1*ch1
#define OUT_CH  16
#define KSTEPS  32      // 512 / 16

// ---------------- device scratch (no allocation allowed) ----------------
__device__ __half2 g_h1h[(size_t)N_MAX * 32];    // x@W1 in fp16 pairs (edge1-only)
__device__ float g_e1s [(size_t)N_MAX * 8];
__device__ float g_e1d [(size_t)N_MAX * 8];
__device__ float g_hact[(size_t)N_MAX * H1F];    // elu(layer1 out)
__device__ __half2 g_h2h[(size_t)N_MAX * 8];     // hact@W2 in fp16 pairs (edge2-only)
__device__ float g_e2s [N_MAX];
__device__ float g_e2d [N_MAX];
__device__ int   g_deg [N_MAX];
__device__ int   g_off [N_MAX + 1];
__device__ int   g_cur [N_MAX];
__device__ int   g_csr [E_MAX];
__device__ int   g_bsum[128];
// W1 pre-packed into mma B-fragment layout (bf16 hi / lo), [ks][nfp][lane]
__device__ uint4 g_wp_h[KSTEPS * 4 * 32];
__device__ uint4 g_wp_l[KSTEPS * 4 * 32];

// ---------------- bf16 split helpers ----------------
// hi = truncate-to-bf16 (top 16 bits); pack pair {f0 -> low half, f1 -> high half}
__device__ __forceinline__ uint32_t hi_pack(float f0, float f1) {
    return __byte_perm(__float_as_uint(f0), __float_as_uint(f1), 0x7632);
}
__device__ __forceinline__ uint32_t lo_pack(float f0, float f1) {
    float l0 = f0 - __uint_as_float(__float_as_uint(f0) & 0xffff0000u);
    float l1 = f1 - __uint_as_float(__float_as_uint(f1) & 0xffff0000u);
    uint32_t r;
    asm("cvt.rn.bf16x2.f32 %0, %1, %2;" : "=r"(r) : "f"(l1), "f"(l0));  // first src -> high half
    return r;
}
__device__ __forceinline__ void mma_bf16(float* d,
                                         uint32_t a0, uint32_t a1, uint32_t a2, uint32_t a3,
                                         uint32_t b0, uint32_t b1) {
    asm("mma.sync.aligned.m16n8k16.row.col.f32.bf16.bf16.f32 "
        "{%0,%1,%2,%3}, {%4,%5,%6,%7}, {%8,%9}, {%0,%1,%2,%3};"
        : "+f"(d[0]), "+f"(d[1]), "+f"(d[2]), "+f"(d[3])
        : "r"(a0), "r"(a1), "r"(a2), "r"(a3), "r"(b0), "r"(b1));
}
__device__ __forceinline__ uint32_t smem_u32(const void* p) {
    uint32_t a;
    asm("{ .reg .u64 t; cvta.to.shared.u64 t, %1; cvt.u32.u64 %0, t; }" : "=r"(a) : "l"(p));
    return a;
}
__device__ __forceinline__ void cpa16(uint32_t dst, const void* src) {
    asm volatile("cp.async.ca.shared.global [%0], [%1], 16;" :: "r"(dst), "l"(src));
}

// ---------------- packed f32x2 helpers (for gemm2) ----------------
__device__ __forceinline__ void fma_f32x2(unsigned long long& acc,
                                          unsigned long long a, unsigned long long b) {
    asm("fma.rn.f32x2 %0, %1, %2, %0;" : "+l"(acc) : "l"(a), "l"(b));
}
__device__ __forceinline__ unsigned long long pack_ff(float v) {
    unsigned long long r;
    asm("mov.b64 %0, {%1, %1};" : "=l"(r) : "f"(v));
    return r;
}
__device__ __forceinline__ void unpack_ff(unsigned long long p, float& lo, float& hi) {
    asm("mov.b64 {%0, %1}, %2;" : "=f"(lo), "=f"(hi) : "l"(p));
}

// ---------------- CSR build ----------------
__global__ void k_zero(int N) {
    int i = blockIdx.x * blockDim.x + threadIdx.x;
    if (i < N) g_deg[i] = 0;
}

__global__ void k_deg(const int* __restrict__ ei, int E_orig, int E_tot) {
    int i = blockIdx.x * blockDim.x + threadIdx.x;
    if (i >= E_tot) return;
    int dst = (i < E_orig) ? ei[E_orig + i] : (i - E_orig);
    atomicAdd(&g_deg[dst], 1);
}

__global__ void k_scanA(int N) {      // grid: ceil(N/1024), block 1024
    __shared__ int s[1024];
    int tid = threadIdx.x;
    int i = blockIdx.x * 1024 + tid;
    int v = (i < N) ? g_deg[i] : 0;
    s[tid] = v;
    __syncthreads();
    for (int o = 1; o < 1024; o <<= 1) {
        int t = (tid >= o) ? s[tid - o] : 0;
        __syncthreads();
        s[tid] += t;
        __syncthreads();
    }
    if (i < N) g_off[i + 1] = s[tid];
    if (tid == 1023) g_bsum[blockIdx.x] = s[1023];
}

__global__ void k_scanB(int nb) {     // <<<1,128>>> parallel scan of block sums
    __shared__ int s[128];
    int tid = threadIdx.x;
    int v = (tid < nb) ? g_bsum[tid] : 0;
    s[tid] = v;
    __syncthreads();
    for (int o = 1; o < 128; o <<= 1) {
        int t = (tid >= o) ? s[tid - o] : 0;
        __syncthreads();
        s[tid] += t;
        __syncthreads();
    }
    if (tid < nb) g_bsum[tid] = s[tid] - v;   // exclusive prefix
}

__global__ void k_scanC(int N) {      // adds block offsets AND fills cursor
    int i = blockIdx.x * blockDim.x + threadIdx.x;
    if (i < N) {
        int v = g_off[i + 1] + g_bsum[i >> 10];
        g_off[i + 1] = v;
        if (i + 1 < N) g_cur[i + 1] = v;
    }
    if (i == 0) { g_off[0] = 0; g_cur[0] = 0; }
}

__global__ void k_scatter(const int* __restrict__ ei, int E_orig, int E_tot) {
    int i = blockIdx.x * blockDim.x + threadIdx.x;
    if (i >= E_tot) return;
    int src, dst;
    if (i < E_orig) { src = ei[i]; dst = ei[E_orig + i]; }
    else            { src = i - E_orig; dst = src; }
    int p = atomicAdd(&g_cur[dst], 1);
    g_csr[p] = src;
}

// ---------------- W1 pre-pack into B-fragment layout ----------------
// B frag (m16n8k16, col): lane l (g=l>>2, t=l&3): b0={B[2t][g],B[2t+1][g]},
// b1={B[2t+8][g],B[2t+9][g]}. uint4 per (ks,nfp,lane) = {nf0.b0, nf0.b1, nf1.b0, nf1.b1}.
__global__ void k_wsplit(const float* __restrict__ W1) {
    int i = blockIdx.x * blockDim.x + threadIdx.x;   // 0 .. 4095
    if (i >= KSTEPS * 4 * 32) return;
    int ks  = i >> 7;
    int nfp = (i >> 5) & 3;
    int l   = i & 31;
    int g = l >> 2, t = l & 3;
    uint32_t h[4], lo[4];
#pragma unroll
    for (int j = 0; j < 4; j++) {
        int nf  = nfp * 2 + (j >> 1);
        int reg = j & 1;
        int k0  = ks * 16 + 2 * t + reg * 8;
        int col = nf * 8 + g;
        float w0 = W1[k0 * 64 + col];
        float w1 = W1[(k0 + 1) * 64 + col];
        h[j]  = hi_pack(w0, w1);
        lo[j] = lo_pack(w0, w1);
    }
    g_wp_h[i] = make_uint4(h[0], h[1], h[2], h[3]);
    g_wp_l[i] = make_uint4(lo[0], lo[1], lo[2], lo[3]);
}

// ---------------- GEMM1 via mma.sync + PER-WARP cp.async pipeline ----------
// Warp = 16 rows x 64 cols; its x rows are warp-private, so each warp runs a
// private 6-deep cp.async ring (1.25KB/stage). NO __syncthreads in mainloop;
// only cp.async.wait_group + __syncwarp. B-frags from L1-hot pre-packed
// globals. bf16 hi/lo split (3 MMAs per tile).
#define G1_STRIDE 20                      // floats per staged row (16 + 4 pad)
#define G1_NSTG   6
#define G1_WSTG   (16 * G1_STRIDE)        // 320 floats per warp-stage
#define G1_SMEM   (8 * G1_NSTG * G1_WSTG * 4)   // 61440 B per CTA

__global__ __launch_bounds__(256, 3) void k_gemm1(
    const float* __restrict__ x,
    const float* __restrict__ a1s, const float* __restrict__ a1d, int N)
{
    extern __shared__ float sx[];
    int t    = threadIdx.x;
    int wid  = t >> 5;
    int lane = t & 31;
    int g = lane >> 2, q = lane & 3;
    int n0 = blockIdx.x * 128;

    float* wbuf = sx + wid * (G1_NSTG * G1_WSTG);
    const uint32_t wbuf_u = smem_u32(wbuf);

    // producer: lane covers rows (lane>>2) and (lane>>2)+8, chunk col lane&3
    int prow = lane >> 2, pc4 = lane & 3;
    int gnA = n0 + wid * 16 + prow;     if (gnA >= N) gnA = 0;
    int gnB = n0 + wid * 16 + prow + 8; if (gnB >= N) gnB = 0;
    const float* srcA = x + (size_t)gnA * IN_CH + pc4 * 4;
    const float* srcB = x + (size_t)gnB * IN_CH + pc4 * 4;
    uint32_t dstA = wbuf_u + (uint32_t)(prow * G1_STRIDE + pc4 * 4) * 4;
    uint32_t dstB = wbuf_u + (uint32_t)((prow + 8) * G1_STRIDE + pc4 * 4) * 4;

    // consumer offsets within a stage
    int ofA = g * G1_STRIDE + 2 * q;
    int ofB = (g + 8) * G1_STRIDE + 2 * q;

    float acc[8][4];
#pragma unroll
    for (int h = 0; h < 8; h++)
#pragma unroll
        for (int c = 0; c < 4; c++) acc[h][c] = 0.f;

    // prologue: stages 0..4 in flight (5 groups)
#pragma unroll
    for (int s = 0; s < 5; s++) {
        uint32_t bo = (uint32_t)(s * G1_WSTG) * 4;
        cpa16(dstA + bo, srcA + s * 16);
        cpa16(dstB + bo, srcB + s * 16);
        asm volatile("cp.async.commit_group;");
    }

    for (int ks = 0; ks < KSTEPS; ks++) {
        asm volatile("cp.async.wait_group 4;");   // stage ks committed
        __syncwarp();
        {
            int kn = ks + 5;
            if (kn < KSTEPS) {
                uint32_t bo = (uint32_t)(((kn) % G1_NSTG) * G1_WSTG) * 4;
                cpa16(dstA + bo, srcA + kn * 16);
                cpa16(dstB + bo, srcB + kn * 16);
            }
            asm volatile("cp.async.commit_group;");   // empty group past end
        }
        const float* sb = wbuf + (ks % G1_NSTG) * G1_WSTG;
        float2 f0 = *reinterpret_cast<const float2*>(sb + ofA);
        float2 f1 = *reinterpret_cast<const float2*>(sb + ofB);
        float2 f2 = *reinterpret_cast<const float2*>(sb + ofA + 8);
        float2 f3 = *reinterpret_cast<const float2*>(sb + ofB + 8);
        uint32_t ah0 = hi_pack(f0.x, f0.y), ah1 = hi_pack(f1.x, f1.y);
        uint32_t ah2 = hi_pack(f2.x, f2.y), ah3 = hi_pack(f3.x, f3.y);
        uint32_t al0 = lo_pack(f0.x, f0.y), al1 = lo_pack(f1.x, f1.y);
        uint32_t al2 = lo_pack(f2.x, f2.y), al3 = lo_pack(f3.x, f3.y);

        const uint4* wph = &g_wp_h[ks * 128 + lane];
        const uint4* wpl = &g_wp_l[ks * 128 + lane];
#pragma unroll
        for (int nfp = 0; nfp < 4; nfp++) {
            uint4 wh = wph[nfp * 32];
            uint4 wl = wpl[nfp * 32];
            mma_bf16(acc[2 * nfp],     ah0, ah1, ah2, ah3, wh.x, wh.y);
            mma_bf16(acc[2 * nfp],     ah0, ah1, ah2, ah3, wl.x, wl.y);
            mma_bf16(acc[2 * nfp],     al0, al1, al2, al3, wh.x, wh.y);
            mma_bf16(acc[2 * nfp + 1], ah0, ah1, ah2, ah3, wh.z, wh.w);
            mma_bf16(acc[2 * nfp + 1], ah0, ah1, ah2, ah3, wl.z, wl.w);
            mma_bf16(acc[2 * nfp + 1], al0, al1, al2, al3, wh.z, wh.w);
        }
    }

    // epilogue: store h1 (fp16 pairs), compute e1s/e1d per head via quad reduce
    int r0 = n0 + wid * 16 + g;
    int r1 = r0 + 8;
    bool ok0 = (r0 < N), ok1 = (r1 < N);
#pragma unroll
    for (int h = 0; h < 8; h++) {
        if (ok0)
            g_h1h[(size_t)r0 * 32 + h * 4 + q] = __floats2half2_rn(acc[h][0], acc[h][1]);
        if (ok1)
            g_h1h[(size_t)r1 * 32 + h * 4 + q] = __floats2half2_rn(acc[h][2], acc[h][3]);
        float2 s = *reinterpret_cast<const float2*>(&a1s[h * 8 + 2 * q]);
        float2 d = *reinterpret_cast<const float2*>(&a1d[h * 8 + 2 * q]);
        float es0 = acc[h][0] * s.x + acc[h][1] * s.y;
        float ed0 = acc[h][0] * d.x + acc[h][1] * d.y;
        float es1 = acc[h][2] * s.x + acc[h][3] * s.y;
        float ed1 = acc[h][2] * d.x + acc[h][3] * d.y;
        es0 += __shfl_xor_sync(0xffffffffu, es0, 1);
        es0 += __shfl_xor_sync(0xffffffffu, es0, 2);
        ed0 += __shfl_xor_sync(0xffffffffu, ed0, 1);
        ed0 += __shfl_xor_sync(0xffffffffu, ed0, 2);
        es1 += __shfl_xor_sync(0xffffffffu, es1, 1);
        es1 += __shfl_xor_sync(0xffffffffu, es1, 2);
        ed1 += __shfl_xor_sync(0xffffffffu, ed1, 1);
        ed1 += __shfl_xor_sync(0xffffffffu, ed1, 2);
        if (q == 0) {
            if (ok0) { g_e1s[r0 * 8 + h] = es0; g_e1d[r0 * 8 + h] = ed0; }
            if (ok1) { g_e1s[r1 * 8 + h] = es1; g_e1d[r1 * 8 + h] = ed1; }
        }
    }
}

// ---------------- layer-1 edge aggregation (warp per dst, fp16 h1) ----------
// Lane l handles features {2l, 2l+1} (same head l>>2): one half2 load, one
// e-stream, one expf per edge per lane. No segment-max needed: logits are
// O(1), exp() safe; alpha = exp(l)/sum exp(l) identical to max-subtracted.
__global__ void k_edge1(const float* __restrict__ b1, int N) {
    int w = (blockIdx.x * blockDim.x + threadIdx.x) >> 5;
    if (w >= N) return;
    int lane = threadIdx.x & 31;
    int h = lane >> 2;               // head for both features
    const float ed = g_e1d[w * 8 + h];
    int beg = g_off[w], end = g_off[w + 1];
    float acc0 = 0.f, acc1 = 0.f, dn = 0.f;
    int i = beg;
    for (; i + 4 <= end; i += 4) {
        int s0 = __ldg(&g_csr[i]);
        int s1 = __ldg(&g_csr[i + 1]);
        int s2 = __ldg(&g_csr[i + 2]);
        int s3 = __ldg(&g_csr[i + 3]);
        float e0 = __ldg(&g_e1s[s0 * 8 + h]);
        float e1 = __ldg(&g_e1s[s1 * 8 + h]);
        float e2 = __ldg(&g_e1s[s2 * 8 + h]);
        float e3 = __ldg(&g_e1s[s3 * 8 + h]);
        __half2 p0 = __ldg(&g_h1h[(size_t)s0 * 32 + lane]);
        __half2 p1 = __ldg(&g_h1h[(size_t)s1 * 32 + lane]);
        __half2 p2 = __ldg(&g_h1h[(size_t)s2 * 32 + lane]);
        __half2 p3 = __ldg(&g_h1h[(size_t)s3 * 32 + lane]);
        float t0 = e0 + ed, t1 = e1 + ed, t2 = e2 + ed, t3 = e3 + ed;
        t0 = t0 > 0.f ? t0 : 0.2f * t0;
        t1 = t1 > 0.f ? t1 : 0.2f * t1;
        t2 = t2 > 0.f ? t2 : 0.2f * t2;
        t3 = t3 > 0.f ? t3 : 0.2f * t3;
        float w0 = __expf(t0), w1 = __expf(t1), w2 = __expf(t2), w3 = __expf(t3);
        float2 v0 = __half22float2(p0);
        float2 v1 = __half22float2(p1);
        float2 v2 = __half22float2(p2);
        float2 v3 = __half22float2(p3);
        acc0 = fmaf(w0, v0.x, acc0); acc1 = fmaf(w0, v0.y, acc1); dn += w0;
        acc0 = fmaf(w1, v1.x, acc0); acc1 = fmaf(w1, v1.y, acc1); dn += w1;
        acc0 = fmaf(w2, v2.x, acc0); acc1 = fmaf(w2, v2.y, acc1); dn += w2;
        acc0 = fmaf(w3, v3.x, acc0); acc1 = fmaf(w3, v3.y, acc1); dn += w3;
    }
    for (; i < end; i++) {
        int s = __ldg(&g_csr[i]);
        float t = __ldg(&g_e1s[s * 8 + h]) + ed;
        t = t > 0.f ? t : 0.2f * t;
        float wt = __expf(t);
        float2 v = __half22float2(__ldg(&g_h1h[(size_t)s * 32 + lane]));
        acc0 = fmaf(wt, v.x, acc0);
        acc1 = fmaf(wt, v.y, acc1);
        dn += wt;
    }
    float2 bb = *reinterpret_cast<const float2*>(&b1[2 * lane]);
    float v0 = acc0 / dn + bb.x;
    float v1 = acc1 / dn + bb.y;
    v0 = v0 > 0.f ? v0 : (__expf(v0) - 1.f);   // ELU
    v1 = v1 > 0.f ? v1 : (__expf(v1) - 1.f);
    *reinterpret_cast<float2*>(&g_hact[(size_t)w * H1F + 2 * lane]) =
        make_float2(v0, v1);
}

// ---------------- GEMM2: h2 = hact @ W2 (+ e2_src/e2_dst), packed f32x2 -------
// h2 stored as fp16 pairs for edge2 (traffic halving); e2s/e2d stay fp32.
__global__ __launch_bounds__(256) void k_gemm2(
    const float* __restrict__ W2, const float* __restrict__ a2s,
    const float* __restrict__ a2d, int N)
{
    __shared__ float hs[64 * 65];
    __shared__ float ws[64 * 16];
    __shared__ float h2s[64 * 17];
    int t  = threadIdx.x;
    int n0 = blockIdx.x * 64;
#pragma unroll
    for (int r = 0; r < 4; r++) {
        int f4   = t + r * 256;
        int node = f4 >> 4;
        int k4   = f4 & 15;
        int gn   = n0 + node;
        float4 v = make_float4(0.f, 0.f, 0.f, 0.f);
        if (gn < N)
            v = *reinterpret_cast<const float4*>(&g_hact[(size_t)gn * H1F + k4 * 4]);
        float* p = &hs[node * 65 + k4 * 4];
        p[0] = v.x; p[1] = v.y; p[2] = v.z; p[3] = v.w;
    }
    {   // W2: 64x16 = 256 float4
        int k  = t >> 2;
        int c4 = t & 3;
        *reinterpret_cast<float4*>(&ws[k * 16 + c4 * 4]) =
            *reinterpret_cast<const float4*>(&W2[k * 16 + c4 * 4]);
    }
    __syncthreads();

    int j  = t >> 2;          // node within tile
    int c0 = (t & 3) * 4;     // output col group
    unsigned long long acc2[2] = {0ULL, 0ULL};
#pragma unroll
    for (int k = 0; k < 64; k++) {
        unsigned long long xp = pack_ff(hs[j * 65 + k]);
        ulonglong2 wv = *reinterpret_cast<const ulonglong2*>(&ws[k * 16 + c0]);
        fma_f32x2(acc2[0], xp, wv.x);
        fma_f32x2(acc2[1], xp, wv.y);
    }
    float acc[4];
    unpack_ff(acc2[0], acc[0], acc[1]);
    unpack_ff(acc2[1], acc[2], acc[3]);
    int gn = n0 + j;
    if (gn < N) {
        g_h2h[(size_t)gn * 8 + (c0 >> 1)]     = __floats2half2_rn(acc[0], acc[1]);
        g_h2h[(size_t)gn * 8 + (c0 >> 1) + 1] = __floats2half2_rn(acc[2], acc[3]);
    }
#pragma unroll
    for (int c = 0; c < 4; c++) h2s[j * 17 + c0 + c] = acc[c];
    __syncthreads();
    if (t < 64) {
        int gn2 = n0 + t;
        if (gn2 < N) {
            float es = 0.f, ed = 0.f;
#pragma unroll
            for (int c = 0; c < OUT_CH; c++) {
                float v = h2s[t * 17 + c];
                es = fmaf(v, a2s[c], es);
                ed = fmaf(v, a2d[c], ed);
            }
            g_e2s[gn2] = es;
            g_e2d[gn2] = ed;
        }
    }
}

// ---------------- layer-2 edge aggregation + fused log_softmax (fp16 h2) -----
// Lane = grp*8 + cp: handles channels {2cp, 2cp+1}, 4 edge streams (grp 0-3).
__global__ void k_edge2(const float* __restrict__ b2, float* __restrict__ out, int N) {
    int w = (blockIdx.x * blockDim.x + threadIdx.x) >> 5;
    if (w >= N) return;
    int lane = threadIdx.x & 31;
    int cp  = lane & 7;
    int grp = lane >> 3;
    float ed = g_e2d[w];
    int beg = g_off[w], end = g_off[w + 1];
    float acc0 = 0.f, acc1 = 0.f, dn = 0.f;
    for (int i = beg + grp; i < end; i += 4) {
        int s = __ldg(&g_csr[i]);
        float t = __ldg(&g_e2s[s]) + ed;
        t = t > 0.f ? t : 0.2f * t;
        float wt = __expf(t);
        float2 v = __half22float2(__ldg(&g_h2h[(size_t)s * 8 + cp]));
        acc0 = fmaf(wt, v.x, acc0);
        acc1 = fmaf(wt, v.y, acc1);
        dn += wt;
    }
    // reduce across the 4 edge streams (lanes with same cp)
    acc0 += __shfl_xor_sync(0xffffffffu, acc0, 8);
    acc0 += __shfl_xor_sync(0xffffffffu, acc0, 16);
    acc1 += __shfl_xor_sync(0xffffffffu, acc1, 8);
    acc1 += __shfl_xor_sync(0xffffffffu, acc1, 16);
    dn   += __shfl_xor_sync(0xffffffffu, dn, 8);
    dn   += __shfl_xor_sync(0xffffffffu, dn, 16);
    float2 bb = *reinterpret_cast<const float2*>(&b2[2 * cp]);
    float v0 = acc0 / dn + bb.x;
    float v1 = acc1 / dn + bb.y;
    // log_softmax over 16 channels spread across 8 lanes (cp) x 2 values
    float m = fmaxf(v0, v1);
#pragma unroll
    for (int o = 1; o < 8; o <<= 1) m = fmaxf(m, __shfl_xor_sync(0xffffffffu, m, o));
    float S = __expf(v0 - m) + __expf(v1 - m);
#pragma unroll
    for (int o = 1; o < 8; o <<= 1) S += __shfl_xor_sync(0xffffffffu, S, o);
    float lS = __logf(S);
    if (grp == 0)
        *reinterpret_cast<float2*>(&out[(size_t)w * OUT_CH + 2 * cp]) =
            make_float2((v0 - m) - lS, (v1 - m) - lS);
}

// ---------------- launch ----------------
extern "C" void kernel_launch(void* const* d_in, const int* in_sizes, int n_in,
                              void* d_out, int out_size)
{
    const float* x   = (const float*)d_in[0];
    const int*   ei  = (const int*)  d_in[1];
    const float* W1  = (const float*)d_in[2];
    const float* a1s = (const float*)d_in[3];
    const float* a1d = (const float*)d_in[4];
    const float* b1  = (const float*)d_in[5];
    const float* W2  = (const float*)d_in[6];
    const float* a2s = (const float*)d_in[7];
    const float* a2d = (const float*)d_in[8];
    const float* b2  = (const float*)d_in[9];
    float* out = (float*)d_out;

    int N      = in_sizes[0] / IN_CH;     // 100000
    int E_orig = in_sizes[1] / 2;         // 3200000
    int E_tot  = E_orig + N;

    cudaFuncSetAttribute(k_gemm1, cudaFuncAttributeMaxDynamicSharedMemorySize, G1_SMEM);

    // gemm1 kept at launch index 3 so the fixed ncu skip-count profiles it.
    k_wsplit <<<16, 256>>>(W1);
    k_zero   <<<(N + 255) / 256, 256>>>(N);
    k_deg    <<<(E_tot + 255) / 256, 256>>>(ei, E_orig, E_tot);
    k_gemm1  <<<(N + 127) / 128, 256, G1_SMEM>>>(x, a1s, a1d, N);
    k_scanA  <<<(N + 1023) / 1024, 1024>>>(N);
    k_scanB  <<<1, 128>>>((N + 1023) / 1024);
    k_scanC  <<<(N + 255) / 256, 256>>>(N);
    k_scatter<<<(E_tot + 255) / 256, 256>>>(ei, E_orig, E_tot);

    // layer 1 aggregation
    k_edge1<<<(N * 32 + 255) / 256, 256>>>(b1, N);

    // layer 2 + fused log_softmax
    k_gemm2<<<(N + 63) / 64, 256>>>(W2, a2s, a2d, N);
    k_edge2<<<(N * 32 + 255) / 256, 256>>>(b2, out, N);
}